// round 9
// baseline (speedup 1.0000x reference)
#include <cuda_runtime.h>
#include <cuda_bf16.h>
#include <cstdint>
#include <math.h>

// Shapes (fixed by the problem)
#define Bb   2
#define SS   1024
#define HH   2048
#define NHH  32
#define NKVV 8
#define DD   64
#define IIF  8192
#define TOK  (Bb*SS)          // 2048 tokens
#define LCK  3

// ================= PTX helpers (arch-neutral: sm_80+ instructions only) ======
__device__ __forceinline__ uint32_t smem_to_u32(const void* p) {
    uint32_t a;
    asm("{ .reg .u64 t; cvta.to.shared.u64 t, %1; cvt.u32.u64 %0, t; }" : "=r"(a) : "l"(p));
    return a;
}

__device__ __forceinline__ void cp16(uint32_t s, const void* g) {
    asm volatile("cp.async.cg.shared.global [%0], [%1], 16;" :: "r"(s), "l"(g) : "memory");
}
#define CP_COMMIT() asm volatile("cp.async.commit_group;" ::: "memory")
#define CP_WAIT(n)  asm volatile("cp.async.wait_group %0;" :: "n"(n) : "memory")

__device__ __forceinline__ void ldsm4(uint32_t* r, uint32_t addr) {
    asm volatile("ldmatrix.sync.aligned.m8n8.x4.shared.b16 {%0,%1,%2,%3}, [%4];"
                 : "=r"(r[0]), "=r"(r[1]), "=r"(r[2]), "=r"(r[3]) : "r"(addr));
}

#define MMA_BF16(c, a, b0, b1)                                            \
    asm volatile("mma.sync.aligned.m16n8k16.row.col.f32.bf16.bf16.f32 "   \
        "{%0,%1,%2,%3}, {%4,%5,%6,%7}, {%8,%9}, {%0,%1,%2,%3};"           \
        : "+f"((c)[0]), "+f"((c)[1]), "+f"((c)[2]), "+f"((c)[3])          \
        : "r"((a)[0]), "r"((a)[1]), "r"((a)[2]), "r"((a)[3]),             \
          "r"(b0), "r"(b1))

// ================= scratch (device globals) =================
__device__ __nv_bfloat16 g_xhi[TOK * 4096],   g_xlo[TOK * 4096];
__device__ __nv_bfloat16 g_wqkv_hi[3072 * 4096],  g_wqkv_lo[3072 * 4096];
__device__ __nv_bfloat16 g_wo_hi[2048 * 2048],    g_wo_lo[2048 * 2048];
__device__ __nv_bfloat16 g_wgu_hi[16384 * 2048],  g_wgu_lo[16384 * 2048];
__device__ __nv_bfloat16 g_wdn_hi[2048 * 8192],   g_wdn_lo[2048 * 8192];
__device__ __nv_bfloat16 g_ahi[TOK * 2048],   g_alo[TOK * 2048];   // attention out
__device__ __nv_bfloat16 g_hnhi[TOK * 2048],  g_hnlo[TOK * 2048];
__device__ __nv_bfloat16 g_acthi[TOK * 8192], g_actlo[TOK * 8192];
__device__ float g_qkv[TOK * 3072];
__device__ float g_q[Bb * NHH * SS * DD];
__device__ float g_k[Bb * NKVV * SS * DD];
__device__ float g_v[Bb * NKVV * SS * DD];
__device__ float g_h2[TOK * 2048];
__device__ float g_gu[TOK * 16384];

__device__ __forceinline__ void split2(float x, __nv_bfloat16& h, __nv_bfloat16& l) {
    h = __float2bfloat16(x);
    l = __float2bfloat16(x - __bfloat162float(h));
}

// ================= tensor-core GEMM (mma.sync bf16, 3-pass split) ============
// C[M,N] = A[M,K] * B[N,K]^T (+resid).  Tile 128x256, BK=32, 512 threads,
// 16 warps (warp tile 64x32). 3-stage cp.async pipeline, 184KB smem.
#define ROWB       80
#define A_BYTES    (128 * ROWB)                // 10240
#define B_BYTES    (256 * ROWB)                // 20480
#define STG_BYTES  (2 * A_BYTES + 2 * B_BYTES) // 61440 (Ah|Al|Bh|Bl)
#define GEMM_DSMEM (3 * STG_BYTES)             // 184320

__device__ __forceinline__ void stage_A(uint32_t sm, const __nv_bfloat16* __restrict__ src,
                                        int row0, int K, int k0, int tid) {
    int row = tid >> 2, c = tid & 3;      // 512 threads -> 128 rows x 4 chunks
    cp16(sm + row * ROWB + c * 16, src + (size_t)(row0 + row) * K + k0 + c * 8);
}
__device__ __forceinline__ void stage_B(uint32_t sm, const __nv_bfloat16* __restrict__ src,
                                        int row0, int K, int k0, int tid) {
#pragma unroll
    for (int h = 0; h < 2; h++) {
        int idx = tid + h * 512;          // 1024 units -> 256 rows x 4 chunks
        int row = idx >> 2, c = idx & 3;
        cp16(sm + row * ROWB + c * 16, src + (size_t)(row0 + row) * K + k0 + c * 8);
    }
}

__device__ __forceinline__ void stage_all(uint32_t u,
    const __nv_bfloat16* __restrict__ Ahi, const __nv_bfloat16* __restrict__ Alo,
    const __nv_bfloat16* __restrict__ Bhi, const __nv_bfloat16* __restrict__ Blo,
    int m0, int n0, int K, int k0, int tid)
{
    stage_A(u,                       Ahi, m0, K, k0, tid);
    stage_A(u + A_BYTES,             Alo, m0, K, k0, tid);
    stage_B(u + 2 * A_BYTES,         Bhi, n0, K, k0, tid);
    stage_B(u + 2 * A_BYTES + B_BYTES, Blo, n0, K, k0, tid);
}

__global__ __launch_bounds__(512, 1) void gemm_mma(
    const __nv_bfloat16* __restrict__ Ahi, const __nv_bfloat16* __restrict__ Alo,
    const __nv_bfloat16* __restrict__ Bhi, const __nv_bfloat16* __restrict__ Blo,
    const float* __restrict__ resid, float* __restrict__ C,
    int ldc, int K, int addResid)
{
    extern __shared__ char dsm[];
    uint32_t sbase = smem_to_u32(dsm);
    int tid = threadIdx.x, wid = tid >> 5, lane = tid & 31;
    int m0 = blockIdx.y * 128, n0 = blockIdx.x * 256;
    int wm = (wid & 1) * 64;          // warp row offset
    int wn = (wid >> 1) * 32;         // warp col offset (0..224)
    int tile = lane >> 3, r = lane & 7;

    float acc[4][4][4];
#pragma unroll
    for (int f = 0; f < 4; f++)
#pragma unroll
        for (int n = 0; n < 4; n++)
#pragma unroll
            for (int e = 0; e < 4; e++) acc[f][n][e] = 0.f;

    int nK = K >> 5;
    // prologue: stages 0,1
#pragma unroll
    for (int s = 0; s < 2; s++) {
        stage_all(sbase + s * STG_BYTES, Ahi, Alo, Bhi, Blo, m0, n0, K, s << 5, tid);
        CP_COMMIT();
    }

    uint32_t aoff = (uint32_t)((((tile & 1) << 3) + r) * ROWB + ((tile >> 1) << 4));
    uint32_t boff = (uint32_t)((((tile >> 1) << 3) + r) * ROWB + ((tile & 1) << 4));

    int buf = 0;
    for (int ks = 0; ks < nK; ks++) {
        int nxt = ks + 2;
        if (nxt < nK) {
            int nb = buf + 2; if (nb >= 3) nb -= 3;
            stage_all(sbase + nb * STG_BYTES, Ahi, Alo, Bhi, Blo, m0, n0, K, nxt << 5, tid);
            CP_COMMIT();
            CP_WAIT(2);
        } else if (ks + 1 < nK) {
            CP_WAIT(1);
        } else {
            CP_WAIT(0);
        }
        __syncthreads();

        uint32_t so = sbase + buf * STG_BYTES;
        uint32_t aHb = so + (uint32_t)(wm * ROWB);
        uint32_t aLb = aHb + A_BYTES;
        uint32_t bHb = so + 2 * A_BYTES + (uint32_t)(wn * ROWB);
        uint32_t bLb = bHb + B_BYTES;

#pragma unroll
        for (int kk = 0; kk < 2; kk++) {
            uint32_t Ah[4][4], Al[4][4], Bh[2][4], Bl[2][4];
            uint32_t kadd = (uint32_t)(kk << 5);
#pragma unroll
            for (int f = 0; f < 4; f++) {
                uint32_t off = aoff + (uint32_t)(f * 16 * ROWB) + kadd;
                ldsm4(Ah[f], aHb + off);
                ldsm4(Al[f], aLb + off);
            }
#pragma unroll
            for (int g = 0; g < 2; g++) {
                uint32_t off = boff + (uint32_t)(g * 16 * ROWB) + kadd;
                ldsm4(Bh[g], bHb + off);
                ldsm4(Bl[g], bLb + off);
            }
#pragma unroll
            for (int f = 0; f < 4; f++) {
#pragma unroll
                for (int n = 0; n < 4; n++) {
                    const uint32_t* bh = &Bh[n >> 1][(n & 1) * 2];
                    const uint32_t* bl = &Bl[n >> 1][(n & 1) * 2];
                    MMA_BF16(acc[f][n], Ah[f], bh[0], bh[1]);
                    MMA_BF16(acc[f][n], Ah[f], bl[0], bl[1]);
                    MMA_BF16(acc[f][n], Al[f], bh[0], bh[1]);
                }
            }
        }
        __syncthreads();
        if (++buf == 3) buf = 0;
    }

    int rr = lane >> 2, cc = (lane & 3) * 2;
#pragma unroll
    for (int f = 0; f < 4; f++) {
#pragma unroll
        for (int n = 0; n < 4; n++) {
            int m = m0 + wm + f * 16 + rr;
            int c = n0 + wn + n * 8 + cc;
            size_t i0 = (size_t)m * ldc + c;
            size_t i1 = (size_t)(m + 8) * ldc + c;
            float2 v0 = make_float2(acc[f][n][0], acc[f][n][1]);
            float2 v1 = make_float2(acc[f][n][2], acc[f][n][3]);
            if (addResid) {
                float2 r0 = *(const float2*)(resid + i0);
                float2 r1 = *(const float2*)(resid + i1);
                v0.x += r0.x; v0.y += r0.y;
                v1.x += r1.x; v1.y += r1.y;
            }
            *(float2*)(C + i0) = v0;
            *(float2*)(C + i1) = v1;
        }
    }
}

// ================= small kernels =================
__device__ __forceinline__ float blockReduceSum(float v) {
    __shared__ float red[8];
    int lane = threadIdx.x & 31, w = threadIdx.x >> 5;
#pragma unroll
    for (int o = 16; o; o >>= 1) v += __shfl_xor_sync(0xffffffffu, v, o);
    if (lane == 0) red[w] = v;
    __syncthreads();
    if (w == 0) {
        float t = (lane < 8) ? red[lane] : 0.0f;
#pragma unroll
        for (int o = 4; o; o >>= 1) t += __shfl_xor_sync(0xffffffffu, t, o);
        if (lane == 0) red[0] = t;
    }
    __syncthreads();
    float r = red[0];
    __syncthreads();
    return r;
}

__global__ __launch_bounds__(256) void rmsnorm_concat_kernel(
    const float* __restrict__ emb, const float* __restrict__ hid,
    const float* __restrict__ w_e, const float* __restrict__ w_h,
    __nv_bfloat16* __restrict__ xhi, __nv_bfloat16* __restrict__ xlo)
{
    int t = blockIdx.x;
    const float* e  = emb + (size_t)t * HH;
    const float* hh = hid + (size_t)t * HH;
    float se = 0.f, sh = 0.f;
    for (int i = threadIdx.x; i < HH; i += 256) {
        float a = e[i];  se += a * a;
        float c = hh[i]; sh += c * c;
    }
    se = blockReduceSum(se);
    sh = blockReduceSum(sh);
    float re = rsqrtf(se / (float)HH + 1e-6f);
    float rh = rsqrtf(sh / (float)HH + 1e-6f);
    size_t ro = (size_t)t * 4096;
    for (int i = threadIdx.x; i < HH; i += 256) {
        __nv_bfloat16 hv, lv;
        split2(w_e[i] * e[i] * re, hv, lv);
        xhi[ro + i] = hv; xlo[ro + i] = lv;
        split2(w_h[i] * hh[i] * rh, hv, lv);
        xhi[ro + HH + i] = hv; xlo[ro + HH + i] = lv;
    }
}

__global__ __launch_bounds__(256) void rmsnorm_split_kernel(
    const float* __restrict__ in, const float* __restrict__ w,
    __nv_bfloat16* __restrict__ ohi, __nv_bfloat16* __restrict__ olo)
{
    int t = blockIdx.x;
    const float* r = in + (size_t)t * HH;
    float s = 0.f;
    for (int i = threadIdx.x; i < HH; i += 256) { float a = r[i]; s += a * a; }
    s = blockReduceSum(s);
    float inv = rsqrtf(s / (float)HH + 1e-6f);
    size_t ro = (size_t)t * HH;
    for (int i = threadIdx.x; i < HH; i += 256) {
        __nv_bfloat16 hv, lv;
        split2(w[i] * r[i] * inv, hv, lv);
        ohi[ro + i] = hv; olo[ro + i] = lv;
    }
}

__global__ __launch_bounds__(256) void convert_split_kernel(
    const float* __restrict__ src, __nv_bfloat16* __restrict__ hi,
    __nv_bfloat16* __restrict__ lo, int n)
{
    int i = (blockIdx.x * 256 + threadIdx.x) * 4;
    if (i < n) {
        float4 v = *(const float4*)(src + i);
        __nv_bfloat16 h0, l0, h1, l1, h2, l2, h3, l3;
        split2(v.x, h0, l0); split2(v.y, h1, l1);
        split2(v.z, h2, l2); split2(v.w, h3, l3);
        __nv_bfloat162* ph = (__nv_bfloat162*)(hi + i);
        __nv_bfloat162* pl = (__nv_bfloat162*)(lo + i);
        ph[0] = __nv_bfloat162(h0, h1); ph[1] = __nv_bfloat162(h2, h3);
        pl[0] = __nv_bfloat162(l0, l1); pl[1] = __nv_bfloat162(l2, l3);
    }
}

// RoPE + layout transform
__global__ __launch_bounds__(256) void rope_kernel(
    const float* __restrict__ qkv, const int* __restrict__ pos_ids,
    float* __restrict__ q, float* __restrict__ k, float* __restrict__ v)
{
    int t = blockIdx.x;
    int b = t >> 10, s = t & 1023;
    float pos = (float)(pos_ids[t] + LCK);
    const float* row = qkv + (size_t)t * 3072;
    const float lg = logf(10000.0f) / 32.0f;

    for (int p = threadIdx.x; p < 1024 + 256; p += 256) {
        const float* src; float* dst; int hh, d;
        if (p < 1024) {
            hh = p >> 5; d = p & 31;
            src = row + hh * 64;
            dst = q + (((size_t)b * NHH + hh) * SS + s) * 64;
        } else {
            int pp = p - 1024;
            hh = pp >> 5; d = pp & 31;
            src = row + 2048 + hh * 64;
            dst = k + (((size_t)b * NKVV + hh) * SS + s) * 64;
        }
        float invf = expf(-(float)d * lg);
        float ang = pos * invf;
        float c = cosf(ang), sn = sinf(ang);
        float x0 = src[d], x1 = src[d + 32];
        dst[d]      = x0 * c - x1 * sn;
        dst[d + 32] = x1 * c + x0 * sn;
    }
    for (int p = threadIdx.x; p < 512; p += 256) {
        int hh = p >> 6, d = p & 63;
        v[(((size_t)b * NKVV + hh) * SS + s) * 64 + d] = row[2560 + p];
    }
}

// attention (flash-style, fp32, NO online-max: scores bounded so exp is safe)
__global__ __launch_bounds__(256) void attn_kernel(
    const float* __restrict__ q, const float* __restrict__ cache_k,
    const float* __restrict__ cache_v, const float* __restrict__ kcur,
    const float* __restrict__ vcur,
    __nv_bfloat16* __restrict__ ohi, __nv_bfloat16* __restrict__ olo)
{
    extern __shared__ float sm[];
    float (*Qs)[68] = (float (*)[68])sm;
    float (*Ks)[68] = (float (*)[68])(sm + 64 * 68);
    float (*Vs)[68] = (float (*)[68])(sm + 2 * 64 * 68);
    float (*sc)[68] = (float (*)[68])(sm + 3 * 64 * 68);
    float* l_s = sm + 4 * 64 * 68;

    int tid = threadIdx.x;
    int tx = tid & 15, ty = tid >> 4;
    int lr = tid >> 2, lc = (tid & 3) << 2;
    int qt = blockIdx.x, h = blockIdx.y, b = blockIdx.z;
    int q0 = qt * 64;
    size_t bh = (size_t)b * NHH + h;
    const float scale = 0.125f;

    {
        const float* qb = q + (bh * SS + q0 + lr) * 64;
#pragma unroll
        for (int dblk = 0; dblk < 4; dblk++) {
            int d = lc + dblk * 16;
            float4 t4 = *(const float4*)(qb + d);
            Qs[d + 0][lr] = t4.x; Qs[d + 1][lr] = t4.y;
            Qs[d + 2][lr] = t4.z; Qs[d + 3][lr] = t4.w;
        }
    }
    if (tid < 64) l_s[tid] = 0.f;

    float acc[4][4];
#pragma unroll
    for (int i = 0; i < 4; i++)
#pragma unroll
        for (int j = 0; j < 4; j++) acc[i][j] = 0.f;

    const float* k0p = cache_k + bh * SS * 64;
    const float* v0p = cache_v + bh * SS * 64;

    for (int kb = 0; kb <= qt; kb++) {
        __syncthreads();
        {
            const float* kp = k0p + (size_t)(kb * 64 + lr) * 64;
            const float* vp = v0p + (size_t)(kb * 64 + lr) * 64;
#pragma unroll
            for (int dblk = 0; dblk < 4; dblk++) {
                int d = lc + dblk * 16;
                float4 k4 = *(const float4*)(kp + d);
                Ks[d + 0][lr] = k4.x; Ks[d + 1][lr] = k4.y;
                Ks[d + 2][lr] = k4.z; Ks[d + 3][lr] = k4.w;
                float4 v4 = *(const float4*)(vp + d);
                *(float4*)&Vs[lr][d] = v4;
            }
        }
        __syncthreads();

        float sreg[4][4];
#pragma unroll
        for (int i = 0; i < 4; i++)
#pragma unroll
            for (int j = 0; j < 4; j++) sreg[i][j] = 0.f;
#pragma unroll 4
        for (int dk = 0; dk < 64; dk++) {
            float4 qa = *(const float4*)&Qs[dk][ty * 4];
            float4 ka = *(const float4*)&Ks[dk][tx * 4];
            float qf[4] = {qa.x, qa.y, qa.z, qa.w};
            float kf[4] = {ka.x, ka.y, ka.z, ka.w};
#pragma unroll
            for (int i = 0; i < 4; i++)
#pragma unroll
                for (int j = 0; j < 4; j++)
                    sreg[i][j] += qf[i] * kf[j];
        }
        // scale + mask + exp + row partial sums, write P
        bool diag = (kb == qt);
        float rs[4];
#pragma unroll
        for (int i = 0; i < 4; i++) {
            rs[i] = 0.f;
#pragma unroll
            for (int j = 0; j < 4; j++) {
                float vv = sreg[i][j] * scale;
                if (diag && (tx * 4 + j) > (ty * 4 + i)) vv = -1e30f;
                vv = __expf(vv);
                sreg[i][j] = vv;
                rs[i] += vv;
            }
            float4 st; st.x = sreg[i][0]; st.y = sreg[i][1]; st.z = sreg[i][2]; st.w = sreg[i][3];
            *(float4*)&sc[ty * 4 + i][tx * 4] = st;
        }
        // reduce row sums across the 16 tx-lanes (lane bits 0..3)
#pragma unroll
        for (int i = 0; i < 4; i++) {
            rs[i] += __shfl_xor_sync(0xffffffffu, rs[i], 1);
            rs[i] += __shfl_xor_sync(0xffffffffu, rs[i], 2);
            rs[i] += __shfl_xor_sync(0xffffffffu, rs[i], 4);
            rs[i] += __shfl_xor_sync(0xffffffffu, rs[i], 8);
        }
        if (tx == 0) {
#pragma unroll
            for (int i = 0; i < 4; i++) l_s[ty * 4 + i] += rs[i];
        }
        __syncthreads();

        // O += P V (no rescale needed)
#pragma unroll 2
        for (int j = 0; j < 64; j++) {
            float4 vv = *(const float4*)&Vs[j][tx * 4];
            float vf[4] = {vv.x, vv.y, vv.z, vv.w};
#pragma unroll
            for (int i = 0; i < 4; i++) {
                float p = sc[ty * 4 + i][j];
#pragma unroll
                for (int jj = 0; jj < 4; jj++) acc[i][jj] += p * vf[jj];
            }
        }
    }

    // ---- 3 extra (diagonal) keys: cache_k[1], cache_k[2], current k ----
    __syncthreads();
    {
        int rr = lr, lane = tid & 3;
        if (lane < 3) {
            int s = q0 + rr;
            const float* kvec;
            if (lane < 2)
                kvec = cache_k + (((size_t)(1 + lane) * Bb * NHH + bh) * SS + s) * 64;
            else
                kvec = kcur + (((size_t)b * NKVV + (h >> 2)) * SS + s) * 64;
            float dot = 0.f;
#pragma unroll 8
            for (int d = 0; d < 64; d++) dot += Qs[d][rr] * kvec[d];
            sc[rr][lane] = __expf(dot * scale);
        }
    }
    __syncthreads();
    if (tx == 0) {
#pragma unroll
        for (int i = 0; i < 4; i++) {
            int rr2 = ty * 4 + i;
            l_s[rr2] += sc[rr2][0] + sc[rr2][1] + sc[rr2][2];
        }
    }
    __syncthreads();
#pragma unroll
    for (int i = 0; i < 4; i++) {
        int s = q0 + ty * 4 + i;
#pragma unroll
        for (int n = 0; n < 3; n++) {
            const float* vvec = (n < 2)
                ? cache_v + (((size_t)(1 + n) * Bb * NHH + bh) * SS + s) * 64
                : vcur + (((size_t)b * NKVV + (h >> 2)) * SS + s) * 64;
            float p = sc[ty * 4 + i][n];
            float4 vv = *(const float4*)(vvec + tx * 4);
            acc[i][0] += p * vv.x; acc[i][1] += p * vv.y;
            acc[i][2] += p * vv.z; acc[i][3] += p * vv.w;
        }
    }
#pragma unroll
    for (int i = 0; i < 4; i++) {
        int s = q0 + ty * 4 + i;
        float inv = 1.0f / l_s[ty * 4 + i];
        size_t oidx = ((size_t)(b * SS + s)) * HH + h * 64 + tx * 4;
#pragma unroll
        for (int j = 0; j < 4; j++) {
            __nv_bfloat16 hv, lv;
            split2(acc[i][j] * inv, hv, lv);
            ohi[oidx + j] = hv;
            olo[oidx + j] = lv;
        }
    }
}

// SiLU(gate)*up -> split bf16 pair
__global__ __launch_bounds__(256) void silu_split_kernel(
    const float* __restrict__ gu, __nv_bfloat16* __restrict__ hi,
    __nv_bfloat16* __restrict__ lo)
{
    int i = blockIdx.x * 256 + threadIdx.x;
    int row = i >> 13, col = i & 8191;
    float g = gu[(size_t)row * 16384 + col];
    float u = gu[(size_t)row * 16384 + 8192 + col];
    float a = g / (1.0f + expf(-g)) * u;
    __nv_bfloat16 hv, lv;
    split2(a, hv, lv);
    hi[i] = hv; lo[i] = lv;
}

// ================= launcher =================
extern "C" void kernel_launch(void* const* d_in, const int* in_sizes, int n_in,
                              void* d_out, int out_size)
{
    const float* input_emb     = (const float*)d_in[0];
    const float* hidden_states = (const float*)d_in[1];
    const float* cache_k       = (const float*)d_in[2];
    const float* cache_v       = (const float*)d_in[3];
    const int*   position_ids  = (const int*)d_in[5];
    const float* wq            = (const float*)d_in[6];
    const float* wk            = (const float*)d_in[7];
    const float* wv            = (const float*)d_in[8];
    const float* wo            = (const float*)d_in[9];
    const float* w_gate        = (const float*)d_in[10];
    const float* w_up          = (const float*)d_in[11];
    const float* w_down        = (const float*)d_in[12];
    const float* hidden_norm_w = (const float*)d_in[13];
    const float* input_ln_w    = (const float*)d_in[14];
    const float* post_ln_w     = (const float*)d_in[15];
    float* out = (float*)d_out;

    __nv_bfloat16 *xhi, *xlo, *wqkvh, *wqkvl, *woh, *wol, *wguh, *wgul, *wdnh, *wdnl;
    __nv_bfloat16 *ahi, *alo, *hnhi, *hnlo, *acth, *actl;
    float *qkv, *q, *k, *v, *h2, *gu;
    cudaGetSymbolAddress((void**)&xhi, g_xhi);     cudaGetSymbolAddress((void**)&xlo, g_xlo);
    cudaGetSymbolAddress((void**)&wqkvh, g_wqkv_hi); cudaGetSymbolAddress((void**)&wqkvl, g_wqkv_lo);
    cudaGetSymbolAddress((void**)&woh, g_wo_hi);   cudaGetSymbolAddress((void**)&wol, g_wo_lo);
    cudaGetSymbolAddress((void**)&wguh, g_wgu_hi); cudaGetSymbolAddress((void**)&wgul, g_wgu_lo);
    cudaGetSymbolAddress((void**)&wdnh, g_wdn_hi); cudaGetSymbolAddress((void**)&wdnl, g_wdn_lo);
    cudaGetSymbolAddress((void**)&ahi, g_ahi);     cudaGetSymbolAddress((void**)&alo, g_alo);
    cudaGetSymbolAddress((void**)&hnhi, g_hnhi);   cudaGetSymbolAddress((void**)&hnlo, g_hnlo);
    cudaGetSymbolAddress((void**)&acth, g_acthi);  cudaGetSymbolAddress((void**)&actl, g_actlo);
    cudaGetSymbolAddress((void**)&qkv, g_qkv);
    cudaGetSymbolAddress((void**)&q, g_q);
    cudaGetSymbolAddress((void**)&k, g_k);
    cudaGetSymbolAddress((void**)&v, g_v);
    cudaGetSymbolAddress((void**)&h2, g_h2);
    cudaGetSymbolAddress((void**)&gu, g_gu);

    cudaFuncSetAttribute(gemm_mma, cudaFuncAttributeMaxDynamicSharedMemorySize, GEMM_DSMEM);
    const int attn_smem = (4 * 64 * 68 + 64) * (int)sizeof(float);
    cudaFuncSetAttribute(attn_kernel, cudaFuncAttributeMaxDynamicSharedMemorySize, attn_smem);

    // weight conversions (fp32 -> bf16 hi/lo), packed QKV and gate|up
    convert_split_kernel<<<2048 * 4096 / 1024, 256>>>(wq, wqkvh, wqkvl, 2048 * 4096);
    convert_split_kernel<<<512 * 4096 / 1024, 256>>>(wk, wqkvh + 2048 * 4096, wqkvl + 2048 * 4096, 512 * 4096);
    convert_split_kernel<<<512 * 4096 / 1024, 256>>>(wv, wqkvh + 2560 * 4096, wqkvl + 2560 * 4096, 512 * 4096);
    convert_split_kernel<<<2048 * 2048 / 1024, 256>>>(wo, woh, wol, 2048 * 2048);
    convert_split_kernel<<<8192 * 2048 / 1024, 256>>>(w_gate, wguh, wgul, 8192 * 2048);
    convert_split_kernel<<<8192 * 2048 / 1024, 256>>>(w_up, wguh + 8192 * 2048, wgul + 8192 * 2048, 8192 * 2048);
    convert_split_kernel<<<2048 * 8192 / 1024, 256>>>(w_down, wdnh, wdnl, 2048 * 8192);

    // 1. norms + concat (split bf16)
    rmsnorm_concat_kernel<<<TOK, 256>>>(input_emb, hidden_states, input_ln_w, hidden_norm_w, xhi, xlo);
    // 2. QKV GEMM (packed, N=3072)
    gemm_mma<<<dim3(3072 / 256, TOK / 128), 512, GEMM_DSMEM>>>(xhi, xlo, wqkvh, wqkvl, nullptr, qkv, 3072, 4096, 0);
    // 3. RoPE + reshape
    rope_kernel<<<TOK, 256>>>(qkv, position_ids, q, k, v);
    // 4. attention -> split bf16
    attn_kernel<<<dim3(SS / 64, NHH, Bb), 256, attn_smem>>>(q, cache_k, cache_v, k, v, ahi, alo);
    // 5. out projection + residual
    gemm_mma<<<dim3(2048 / 256, TOK / 128), 512, GEMM_DSMEM>>>(ahi, alo, woh, wol, hidden_states, h2, 2048, 2048, 1);
    // 6. post-attn norm -> split bf16
    rmsnorm_split_kernel<<<TOK, 256>>>(h2, post_ln_w, hnhi, hnlo);
    // 7. gate|up GEMM (packed, N=16384)
    gemm_mma<<<dim3(16384 / 256, TOK / 128), 512, GEMM_DSMEM>>>(hnhi, hnlo, wguh, wgul, nullptr, gu, 16384, 2048, 0);
    // 8. SiLU * up -> split bf16
    silu_split_kernel<<<TOK * IIF / 256, 256>>>(gu, acth, actl);
    // 9. down projection + residual -> final output
    gemm_mma<<<dim3(2048 / 256, TOK / 128), 512, GEMM_DSMEM>>>(acth, actl, wdnh, wdnl, h2, out, 2048, 8192, 1);

    (void)in_sizes; (void)n_in; (void)out_size;
}

// round 10
// speedup vs baseline: 1.1196x; 1.1196x over previous
#include <cuda_runtime.h>
#include <cuda_bf16.h>
#include <cstdint>
#include <math.h>

// Shapes (fixed by the problem)
#define Bb   2
#define SS   1024
#define HH   2048
#define NHH  32
#define NKVV 8
#define DD   64
#define IIF  8192
#define TOK  (Bb*SS)          // 2048 tokens
#define LCK  3

// ================= PTX helpers (arch-neutral: sm_80+ instructions only) ======
__device__ __forceinline__ uint32_t smem_to_u32(const void* p) {
    uint32_t a;
    asm("{ .reg .u64 t; cvta.to.shared.u64 t, %1; cvt.u32.u64 %0, t; }" : "=r"(a) : "l"(p));
    return a;
}

__device__ __forceinline__ void cp16(uint32_t s, const void* g) {
    asm volatile("cp.async.cg.shared.global [%0], [%1], 16;" :: "r"(s), "l"(g) : "memory");
}
#define CP_COMMIT() asm volatile("cp.async.commit_group;" ::: "memory")
#define CP_WAIT(n)  asm volatile("cp.async.wait_group %0;" :: "n"(n) : "memory")

__device__ __forceinline__ void ldsm4(uint32_t* r, uint32_t addr) {
    asm volatile("ldmatrix.sync.aligned.m8n8.x4.shared.b16 {%0,%1,%2,%3}, [%4];"
                 : "=r"(r[0]), "=r"(r[1]), "=r"(r[2]), "=r"(r[3]) : "r"(addr));
}

#define MMA_BF16(c, a, b0, b1)                                            \
    asm volatile("mma.sync.aligned.m16n8k16.row.col.f32.bf16.bf16.f32 "   \
        "{%0,%1,%2,%3}, {%4,%5,%6,%7}, {%8,%9}, {%0,%1,%2,%3};"           \
        : "+f"((c)[0]), "+f"((c)[1]), "+f"((c)[2]), "+f"((c)[3])          \
        : "r"((a)[0]), "r"((a)[1]), "r"((a)[2]), "r"((a)[3]),             \
          "r"(b0), "r"(b1))

// ================= scratch (device globals) =================
__device__ __nv_bfloat16 g_xhi[TOK * 4096],   g_xlo[TOK * 4096];
__device__ __nv_bfloat16 g_wqkv_hi[3072 * 4096],  g_wqkv_lo[3072 * 4096];
__device__ __nv_bfloat16 g_wo_hi[2048 * 2048],    g_wo_lo[2048 * 2048];
__device__ __nv_bfloat16 g_wgu_hi[16384 * 2048],  g_wgu_lo[16384 * 2048];
__device__ __nv_bfloat16 g_wdn_hi[2048 * 8192],   g_wdn_lo[2048 * 8192];
__device__ __nv_bfloat16 g_ahi[TOK * 2048],   g_alo[TOK * 2048];   // attention out
__device__ __nv_bfloat16 g_hnhi[TOK * 2048],  g_hnlo[TOK * 2048];
__device__ __nv_bfloat16 g_acthi[TOK * 8192], g_actlo[TOK * 8192];
__device__ float g_qkv[TOK * 3072];
__device__ float g_q[Bb * NHH * SS * DD];
__device__ float g_k[Bb * NKVV * SS * DD];
__device__ float g_v[Bb * NKVV * SS * DD];
__device__ float g_h2[TOK * 2048];
__device__ float g_gu[TOK * 16384];

__device__ __forceinline__ void split2(float x, __nv_bfloat16& h, __nv_bfloat16& l) {
    h = __float2bfloat16(x);
    l = __float2bfloat16(x - __bfloat162float(h));
}

// ================= tensor-core GEMM (mma.sync bf16, 3-pass split) ============
// C[M,N] = A[M,K] * B[N,K]^T (+resid).  Tile 128x128, BK=32, 256 threads.
// 2-stage cp.async pipeline, 80KB smem -> 2 CTAs/SM for latency hiding.
#define ROWB       80
#define MAT_BYTES  (128 * ROWB)
#define STG_BYTES  (4 * MAT_BYTES)       // 40960 (Ah | Al | Bh | Bl)
#define GEMM_DSMEM (2 * STG_BYTES)       // 81920

__device__ __forceinline__ void stage_mat(uint32_t smat, const __nv_bfloat16* __restrict__ src,
                                          int row0, int K, int k0, int tid) {
#pragma unroll
    for (int h = 0; h < 2; h++) {
        int idx = tid + h * 256;
        int row = idx >> 2, c = idx & 3;
        cp16(smat + row * ROWB + c * 16,
             src + (size_t)(row0 + row) * K + k0 + c * 8);
    }
}

__global__ __launch_bounds__(256, 2) void gemm_mma(
    const __nv_bfloat16* __restrict__ Ahi, const __nv_bfloat16* __restrict__ Alo,
    const __nv_bfloat16* __restrict__ Bhi, const __nv_bfloat16* __restrict__ Blo,
    const float* __restrict__ resid, float* __restrict__ C,
    int ldc, int K, int addResid)
{
    extern __shared__ char dsm[];
    uint32_t sbase = smem_to_u32(dsm);
    int tid = threadIdx.x, wid = tid >> 5, lane = tid & 31;
    int m0 = blockIdx.y * 128, n0 = blockIdx.x * 128;
    int wm = (wid & 1) * 64;
    int wn = (wid >> 1) * 32;
    int tile = lane >> 3, r = lane & 7;

    float acc[4][4][4];
#pragma unroll
    for (int f = 0; f < 4; f++)
#pragma unroll
        for (int n = 0; n < 4; n++)
#pragma unroll
            for (int e = 0; e < 4; e++) acc[f][n][e] = 0.f;

    int nK = K >> 5;
    // prologue: stage 0
    {
        stage_mat(sbase,                 Ahi, m0, K, 0, tid);
        stage_mat(sbase + MAT_BYTES,     Alo, m0, K, 0, tid);
        stage_mat(sbase + 2 * MAT_BYTES, Bhi, n0, K, 0, tid);
        stage_mat(sbase + 3 * MAT_BYTES, Blo, n0, K, 0, tid);
        CP_COMMIT();
    }

    uint32_t aoff = (uint32_t)((((tile & 1) << 3) + r) * ROWB + ((tile >> 1) << 4));
    uint32_t boff = (uint32_t)((((tile >> 1) << 3) + r) * ROWB + ((tile & 1) << 4));

    for (int ks = 0; ks < nK; ks++) {
        int nxt = ks + 1;
        if (nxt < nK) {
            uint32_t sp = sbase + (nxt & 1) * STG_BYTES;
            int k0 = nxt << 5;
            stage_mat(sp,                 Ahi, m0, K, k0, tid);
            stage_mat(sp + MAT_BYTES,     Alo, m0, K, k0, tid);
            stage_mat(sp + 2 * MAT_BYTES, Bhi, n0, K, k0, tid);
            stage_mat(sp + 3 * MAT_BYTES, Blo, n0, K, k0, tid);
            CP_COMMIT();
            CP_WAIT(1);
        } else {
            CP_WAIT(0);
        }
        __syncthreads();

        uint32_t so = sbase + (ks & 1) * STG_BYTES;
        uint32_t aHb = so + (uint32_t)(wm * ROWB);
        uint32_t aLb = aHb + MAT_BYTES;
        uint32_t bHb = so + 2 * MAT_BYTES + (uint32_t)(wn * ROWB);
        uint32_t bLb = bHb + MAT_BYTES;

#pragma unroll
        for (int kk = 0; kk < 2; kk++) {
            uint32_t Ah[4][4], Al[4][4], Bh[2][4], Bl[2][4];
            uint32_t kadd = (uint32_t)(kk << 5);
#pragma unroll
            for (int f = 0; f < 4; f++) {
                uint32_t off = aoff + (uint32_t)(f * 16 * ROWB) + kadd;
                ldsm4(Ah[f], aHb + off);
                ldsm4(Al[f], aLb + off);
            }
#pragma unroll
            for (int g = 0; g < 2; g++) {
                uint32_t off = boff + (uint32_t)(g * 16 * ROWB) + kadd;
                ldsm4(Bh[g], bHb + off);
                ldsm4(Bl[g], bLb + off);
            }
#pragma unroll
            for (int f = 0; f < 4; f++) {
#pragma unroll
                for (int n = 0; n < 4; n++) {
                    const uint32_t* bh = &Bh[n >> 1][(n & 1) * 2];
                    const uint32_t* bl = &Bl[n >> 1][(n & 1) * 2];
                    MMA_BF16(acc[f][n], Ah[f], bh[0], bh[1]);
                    MMA_BF16(acc[f][n], Ah[f], bl[0], bl[1]);
                    MMA_BF16(acc[f][n], Al[f], bh[0], bh[1]);
                }
            }
        }
        __syncthreads();
    }

    int rr = lane >> 2, cc = (lane & 3) * 2;
#pragma unroll
    for (int f = 0; f < 4; f++) {
#pragma unroll
        for (int n = 0; n < 4; n++) {
            int m = m0 + wm + f * 16 + rr;
            int c = n0 + wn + n * 8 + cc;
            size_t i0 = (size_t)m * ldc + c;
            size_t i1 = (size_t)(m + 8) * ldc + c;
            float2 v0 = make_float2(acc[f][n][0], acc[f][n][1]);
            float2 v1 = make_float2(acc[f][n][2], acc[f][n][3]);
            if (addResid) {
                float2 r0 = *(const float2*)(resid + i0);
                float2 r1 = *(const float2*)(resid + i1);
                v0.x += r0.x; v0.y += r0.y;
                v1.x += r1.x; v1.y += r1.y;
            }
            *(float2*)(C + i0) = v0;
            *(float2*)(C + i1) = v1;
        }
    }
}

// ================= small kernels =================
__device__ __forceinline__ float blockReduceSum(float v) {
    __shared__ float red[8];
    int lane = threadIdx.x & 31, w = threadIdx.x >> 5;
#pragma unroll
    for (int o = 16; o; o >>= 1) v += __shfl_xor_sync(0xffffffffu, v, o);
    if (lane == 0) red[w] = v;
    __syncthreads();
    if (w == 0) {
        float t = (lane < 8) ? red[lane] : 0.0f;
#pragma unroll
        for (int o = 4; o; o >>= 1) t += __shfl_xor_sync(0xffffffffu, t, o);
        if (lane == 0) red[0] = t;
    }
    __syncthreads();
    float r = red[0];
    __syncthreads();
    return r;
}

__global__ __launch_bounds__(256) void rmsnorm_concat_kernel(
    const float* __restrict__ emb, const float* __restrict__ hid,
    const float* __restrict__ w_e, const float* __restrict__ w_h,
    __nv_bfloat16* __restrict__ xhi, __nv_bfloat16* __restrict__ xlo)
{
    int t = blockIdx.x;
    const float* e  = emb + (size_t)t * HH;
    const float* hh = hid + (size_t)t * HH;
    float se = 0.f, sh = 0.f;
    for (int i = threadIdx.x; i < HH; i += 256) {
        float a = e[i];  se += a * a;
        float c = hh[i]; sh += c * c;
    }
    se = blockReduceSum(se);
    sh = blockReduceSum(sh);
    float re = rsqrtf(se / (float)HH + 1e-6f);
    float rh = rsqrtf(sh / (float)HH + 1e-6f);
    size_t ro = (size_t)t * 4096;
    for (int i = threadIdx.x; i < HH; i += 256) {
        __nv_bfloat16 hv, lv;
        split2(w_e[i] * e[i] * re, hv, lv);
        xhi[ro + i] = hv; xlo[ro + i] = lv;
        split2(w_h[i] * hh[i] * rh, hv, lv);
        xhi[ro + HH + i] = hv; xlo[ro + HH + i] = lv;
    }
}

__global__ __launch_bounds__(256) void rmsnorm_split_kernel(
    const float* __restrict__ in, const float* __restrict__ w,
    __nv_bfloat16* __restrict__ ohi, __nv_bfloat16* __restrict__ olo)
{
    int t = blockIdx.x;
    const float* r = in + (size_t)t * HH;
    float s = 0.f;
    for (int i = threadIdx.x; i < HH; i += 256) { float a = r[i]; s += a * a; }
    s = blockReduceSum(s);
    float inv = rsqrtf(s / (float)HH + 1e-6f);
    size_t ro = (size_t)t * HH;
    for (int i = threadIdx.x; i < HH; i += 256) {
        __nv_bfloat16 hv, lv;
        split2(w[i] * r[i] * inv, hv, lv);
        ohi[ro + i] = hv; olo[ro + i] = lv;
    }
}

__global__ __launch_bounds__(256) void convert_split_kernel(
    const float* __restrict__ src, __nv_bfloat16* __restrict__ hi,
    __nv_bfloat16* __restrict__ lo, int n)
{
    int i = (blockIdx.x * 256 + threadIdx.x) * 4;
    if (i < n) {
        float4 v = *(const float4*)(src + i);
        __nv_bfloat16 h0, l0, h1, l1, h2, l2, h3, l3;
        split2(v.x, h0, l0); split2(v.y, h1, l1);
        split2(v.z, h2, l2); split2(v.w, h3, l3);
        __nv_bfloat162* ph = (__nv_bfloat162*)(hi + i);
        __nv_bfloat162* pl = (__nv_bfloat162*)(lo + i);
        ph[0] = __nv_bfloat162(h0, h1); ph[1] = __nv_bfloat162(h2, h3);
        pl[0] = __nv_bfloat162(l0, l1); pl[1] = __nv_bfloat162(l2, l3);
    }
}

// RoPE + layout transform
__global__ __launch_bounds__(256) void rope_kernel(
    const float* __restrict__ qkv, const int* __restrict__ pos_ids,
    float* __restrict__ q, float* __restrict__ k, float* __restrict__ v)
{
    int t = blockIdx.x;
    int b = t >> 10, s = t & 1023;
    float pos = (float)(pos_ids[t] + LCK);
    const float* row = qkv + (size_t)t * 3072;
    const float lg = logf(10000.0f) / 32.0f;

    for (int p = threadIdx.x; p < 1024 + 256; p += 256) {
        const float* src; float* dst; int hh, d;
        if (p < 1024) {
            hh = p >> 5; d = p & 31;
            src = row + hh * 64;
            dst = q + (((size_t)b * NHH + hh) * SS + s) * 64;
        } else {
            int pp = p - 1024;
            hh = pp >> 5; d = pp & 31;
            src = row + 2048 + hh * 64;
            dst = k + (((size_t)b * NKVV + hh) * SS + s) * 64;
        }
        float invf = expf(-(float)d * lg);
        float ang = pos * invf;
        float c = cosf(ang), sn = sinf(ang);
        float x0 = src[d], x1 = src[d + 32];
        dst[d]      = x0 * c - x1 * sn;
        dst[d + 32] = x1 * c + x0 * sn;
    }
    for (int p = threadIdx.x; p < 512; p += 256) {
        int hh = p >> 6, d = p & 63;
        v[(((size_t)b * NKVV + hh) * SS + s) * 64 + d] = row[2560 + p];
    }
}

// attention (flash-style, fp32, NO online-max: scores bounded so exp is safe)
__global__ __launch_bounds__(256) void attn_kernel(
    const float* __restrict__ q, const float* __restrict__ cache_k,
    const float* __restrict__ cache_v, const float* __restrict__ kcur,
    const float* __restrict__ vcur,
    __nv_bfloat16* __restrict__ ohi, __nv_bfloat16* __restrict__ olo)
{
    extern __shared__ float sm[];
    float (*Qs)[68] = (float (*)[68])sm;
    float (*Ks)[68] = (float (*)[68])(sm + 64 * 68);
    float (*Vs)[68] = (float (*)[68])(sm + 2 * 64 * 68);
    float (*sc)[68] = (float (*)[68])(sm + 3 * 64 * 68);
    float* l_s = sm + 4 * 64 * 68;

    int tid = threadIdx.x;
    int tx = tid & 15, ty = tid >> 4;
    int lr = tid >> 2, lc = (tid & 3) << 2;
    int qt = blockIdx.x, h = blockIdx.y, b = blockIdx.z;
    int q0 = qt * 64;
    size_t bh = (size_t)b * NHH + h;
    const float scale = 0.125f;

    {
        const float* qb = q + (bh * SS + q0 + lr) * 64;
#pragma unroll
        for (int dblk = 0; dblk < 4; dblk++) {
            int d = lc + dblk * 16;
            float4 t4 = *(const float4*)(qb + d);
            Qs[d + 0][lr] = t4.x; Qs[d + 1][lr] = t4.y;
            Qs[d + 2][lr] = t4.z; Qs[d + 3][lr] = t4.w;
        }
    }
    if (tid < 64) l_s[tid] = 0.f;

    float acc[4][4];
#pragma unroll
    for (int i = 0; i < 4; i++)
#pragma unroll
        for (int j = 0; j < 4; j++) acc[i][j] = 0.f;

    const float* k0p = cache_k + bh * SS * 64;
    const float* v0p = cache_v + bh * SS * 64;

    for (int kb = 0; kb <= qt; kb++) {
        __syncthreads();
        {
            const float* kp = k0p + (size_t)(kb * 64 + lr) * 64;
            const float* vp = v0p + (size_t)(kb * 64 + lr) * 64;
#pragma unroll
            for (int dblk = 0; dblk < 4; dblk++) {
                int d = lc + dblk * 16;
                float4 k4 = *(const float4*)(kp + d);
                Ks[d + 0][lr] = k4.x; Ks[d + 1][lr] = k4.y;
                Ks[d + 2][lr] = k4.z; Ks[d + 3][lr] = k4.w;
                float4 v4 = *(const float4*)(vp + d);
                *(float4*)&Vs[lr][d] = v4;
            }
        }
        __syncthreads();

        float sreg[4][4];
#pragma unroll
        for (int i = 0; i < 4; i++)
#pragma unroll
            for (int j = 0; j < 4; j++) sreg[i][j] = 0.f;
#pragma unroll 4
        for (int dk = 0; dk < 64; dk++) {
            float4 qa = *(const float4*)&Qs[dk][ty * 4];
            float4 ka = *(const float4*)&Ks[dk][tx * 4];
            float qf[4] = {qa.x, qa.y, qa.z, qa.w};
            float kf[4] = {ka.x, ka.y, ka.z, ka.w};
#pragma unroll
            for (int i = 0; i < 4; i++)
#pragma unroll
                for (int j = 0; j < 4; j++)
                    sreg[i][j] += qf[i] * kf[j];
        }
        // scale + mask + exp + row partial sums, write P
        bool diag = (kb == qt);
        float rs[4];
#pragma unroll
        for (int i = 0; i < 4; i++) {
            rs[i] = 0.f;
#pragma unroll
            for (int j = 0; j < 4; j++) {
                float vv = sreg[i][j] * scale;
                if (diag && (tx * 4 + j) > (ty * 4 + i)) vv = -1e30f;
                vv = __expf(vv);
                sreg[i][j] = vv;
                rs[i] += vv;
            }
            float4 st; st.x = sreg[i][0]; st.y = sreg[i][1]; st.z = sreg[i][2]; st.w = sreg[i][3];
            *(float4*)&sc[ty * 4 + i][tx * 4] = st;
        }
        // reduce row sums across the 16 tx-lanes (lane bits 0..3)
#pragma unroll
        for (int i = 0; i < 4; i++) {
            rs[i] += __shfl_xor_sync(0xffffffffu, rs[i], 1);
            rs[i] += __shfl_xor_sync(0xffffffffu, rs[i], 2);
            rs[i] += __shfl_xor_sync(0xffffffffu, rs[i], 4);
            rs[i] += __shfl_xor_sync(0xffffffffu, rs[i], 8);
        }
        if (tx == 0) {
#pragma unroll
            for (int i = 0; i < 4; i++) l_s[ty * 4 + i] += rs[i];
        }
        __syncthreads();

        // O += P V (no rescale needed)
#pragma unroll 2
        for (int j = 0; j < 64; j++) {
            float4 vv = *(const float4*)&Vs[j][tx * 4];
            float vf[4] = {vv.x, vv.y, vv.z, vv.w};
#pragma unroll
            for (int i = 0; i < 4; i++) {
                float p = sc[ty * 4 + i][j];
#pragma unroll
                for (int jj = 0; jj < 4; jj++) acc[i][jj] += p * vf[jj];
            }
        }
    }

    // ---- 3 extra (diagonal) keys: cache_k[1], cache_k[2], current k ----
    __syncthreads();
    {
        int rr = lr, lane = tid & 3;
        if (lane < 3) {
            int s = q0 + rr;
            const float* kvec;
            if (lane < 2)
                kvec = cache_k + (((size_t)(1 + lane) * Bb * NHH + bh) * SS + s) * 64;
            else
                kvec = kcur + (((size_t)b * NKVV + (h >> 2)) * SS + s) * 64;
            float dot = 0.f;
#pragma unroll 8
            for (int d = 0; d < 64; d++) dot += Qs[d][rr] * kvec[d];
            sc[rr][lane] = __expf(dot * scale);
        }
    }
    __syncthreads();
    if (tx == 0) {
#pragma unroll
        for (int i = 0; i < 4; i++) {
            int rr2 = ty * 4 + i;
            l_s[rr2] += sc[rr2][0] + sc[rr2][1] + sc[rr2][2];
        }
    }
    __syncthreads();
#pragma unroll
    for (int i = 0; i < 4; i++) {
        int s = q0 + ty * 4 + i;
#pragma unroll
        for (int n = 0; n < 3; n++) {
            const float* vvec = (n < 2)
                ? cache_v + (((size_t)(1 + n) * Bb * NHH + bh) * SS + s) * 64
                : vcur + (((size_t)b * NKVV + (h >> 2)) * SS + s) * 64;
            float p = sc[ty * 4 + i][n];
            float4 vv = *(const float4*)(vvec + tx * 4);
            acc[i][0] += p * vv.x; acc[i][1] += p * vv.y;
            acc[i][2] += p * vv.z; acc[i][3] += p * vv.w;
        }
    }
#pragma unroll
    for (int i = 0; i < 4; i++) {
        int s = q0 + ty * 4 + i;
        float inv = 1.0f / l_s[ty * 4 + i];
        size_t oidx = ((size_t)(b * SS + s)) * HH + h * 64 + tx * 4;
#pragma unroll
        for (int j = 0; j < 4; j++) {
            __nv_bfloat16 hv, lv;
            split2(acc[i][j] * inv, hv, lv);
            ohi[oidx + j] = hv;
            olo[oidx + j] = lv;
        }
    }
}

// SiLU(gate)*up -> split bf16 pair
__global__ __launch_bounds__(256) void silu_split_kernel(
    const float* __restrict__ gu, __nv_bfloat16* __restrict__ hi,
    __nv_bfloat16* __restrict__ lo)
{
    int i = blockIdx.x * 256 + threadIdx.x;
    int row = i >> 13, col = i & 8191;
    float g = gu[(size_t)row * 16384 + col];
    float u = gu[(size_t)row * 16384 + 8192 + col];
    float a = g / (1.0f + expf(-g)) * u;
    __nv_bfloat16 hv, lv;
    split2(a, hv, lv);
    hi[i] = hv; lo[i] = lv;
}

// ================= launcher =================
extern "C" void kernel_launch(void* const* d_in, const int* in_sizes, int n_in,
                              void* d_out, int out_size)
{
    const float* input_emb     = (const float*)d_in[0];
    const float* hidden_states = (const float*)d_in[1];
    const float* cache_k       = (const float*)d_in[2];
    const float* cache_v       = (const float*)d_in[3];
    const int*   position_ids  = (const int*)d_in[5];
    const float* wq            = (const float*)d_in[6];
    const float* wk            = (const float*)d_in[7];
    const float* wv            = (const float*)d_in[8];
    const float* wo            = (const float*)d_in[9];
    const float* w_gate        = (const float*)d_in[10];
    const float* w_up          = (const float*)d_in[11];
    const float* w_down        = (const float*)d_in[12];
    const float* hidden_norm_w = (const float*)d_in[13];
    const float* input_ln_w    = (const float*)d_in[14];
    const float* post_ln_w     = (const float*)d_in[15];
    float* out = (float*)d_out;

    __nv_bfloat16 *xhi, *xlo, *wqkvh, *wqkvl, *woh, *wol, *wguh, *wgul, *wdnh, *wdnl;
    __nv_bfloat16 *ahi, *alo, *hnhi, *hnlo, *acth, *actl;
    float *qkv, *q, *k, *v, *h2, *gu;
    cudaGetSymbolAddress((void**)&xhi, g_xhi);     cudaGetSymbolAddress((void**)&xlo, g_xlo);
    cudaGetSymbolAddress((void**)&wqkvh, g_wqkv_hi); cudaGetSymbolAddress((void**)&wqkvl, g_wqkv_lo);
    cudaGetSymbolAddress((void**)&woh, g_wo_hi);   cudaGetSymbolAddress((void**)&wol, g_wo_lo);
    cudaGetSymbolAddress((void**)&wguh, g_wgu_hi); cudaGetSymbolAddress((void**)&wgul, g_wgu_lo);
    cudaGetSymbolAddress((void**)&wdnh, g_wdn_hi); cudaGetSymbolAddress((void**)&wdnl, g_wdn_lo);
    cudaGetSymbolAddress((void**)&ahi, g_ahi);     cudaGetSymbolAddress((void**)&alo, g_alo);
    cudaGetSymbolAddress((void**)&hnhi, g_hnhi);   cudaGetSymbolAddress((void**)&hnlo, g_hnlo);
    cudaGetSymbolAddress((void**)&acth, g_acthi);  cudaGetSymbolAddress((void**)&actl, g_actlo);
    cudaGetSymbolAddress((void**)&qkv, g_qkv);
    cudaGetSymbolAddress((void**)&q, g_q);
    cudaGetSymbolAddress((void**)&k, g_k);
    cudaGetSymbolAddress((void**)&v, g_v);
    cudaGetSymbolAddress((void**)&h2, g_h2);
    cudaGetSymbolAddress((void**)&gu, g_gu);

    cudaFuncSetAttribute(gemm_mma, cudaFuncAttributeMaxDynamicSharedMemorySize, GEMM_DSMEM);
    const int attn_smem = (4 * 64 * 68 + 64) * (int)sizeof(float);
    cudaFuncSetAttribute(attn_kernel, cudaFuncAttributeMaxDynamicSharedMemorySize, attn_smem);

    // weight conversions (fp32 -> bf16 hi/lo), packed QKV and gate|up
    convert_split_kernel<<<2048 * 4096 / 1024, 256>>>(wq, wqkvh, wqkvl, 2048 * 4096);
    convert_split_kernel<<<512 * 4096 / 1024, 256>>>(wk, wqkvh + 2048 * 4096, wqkvl + 2048 * 4096, 512 * 4096);
    convert_split_kernel<<<512 * 4096 / 1024, 256>>>(wv, wqkvh + 2560 * 4096, wqkvl + 2560 * 4096, 512 * 4096);
    convert_split_kernel<<<2048 * 2048 / 1024, 256>>>(wo, woh, wol, 2048 * 2048);
    convert_split_kernel<<<8192 * 2048 / 1024, 256>>>(w_gate, wguh, wgul, 8192 * 2048);
    convert_split_kernel<<<8192 * 2048 / 1024, 256>>>(w_up, wguh + 8192 * 2048, wgul + 8192 * 2048, 8192 * 2048);
    convert_split_kernel<<<2048 * 8192 / 1024, 256>>>(w_down, wdnh, wdnl, 2048 * 8192);

    // 1. norms + concat (split bf16)
    rmsnorm_concat_kernel<<<TOK, 256>>>(input_emb, hidden_states, input_ln_w, hidden_norm_w, xhi, xlo);
    // 2. QKV GEMM (packed, N=3072)
    gemm_mma<<<dim3(3072 / 128, TOK / 128), 256, GEMM_DSMEM>>>(xhi, xlo, wqkvh, wqkvl, nullptr, qkv, 3072, 4096, 0);
    // 3. RoPE + reshape
    rope_kernel<<<TOK, 256>>>(qkv, position_ids, q, k, v);
    // 4. attention -> split bf16
    attn_kernel<<<dim3(SS / 64, NHH, Bb), 256, attn_smem>>>(q, cache_k, cache_v, k, v, ahi, alo);
    // 5. out projection + residual
    gemm_mma<<<dim3(2048 / 128, TOK / 128), 256, GEMM_DSMEM>>>(ahi, alo, woh, wol, hidden_states, h2, 2048, 2048, 1);
    // 6. post-attn norm -> split bf16
    rmsnorm_split_kernel<<<TOK, 256>>>(h2, post_ln_w, hnhi, hnlo);
    // 7. gate|up GEMM (packed, N=16384)
    gemm_mma<<<dim3(16384 / 128, TOK / 128), 256, GEMM_DSMEM>>>(hnhi, hnlo, wguh, wgul, nullptr, gu, 16384, 2048, 0);
    // 8. SiLU * up -> split bf16
    silu_split_kernel<<<TOK * IIF / 256, 256>>>(gu, acth, actl);
    // 9. down projection + residual -> final output
    gemm_mma<<<dim3(2048 / 128, TOK / 128), 256, GEMM_DSMEM>>>(acth, actl, wdnh, wdnl, h2, out, 2048, 8192, 1);

    (void)in_sizes; (void)n_in; (void)out_size;
}

// round 12
// speedup vs baseline: 1.1213x; 1.0016x over previous
#include <cuda_runtime.h>
#include <cuda_bf16.h>
#include <cstdint>
#include <math.h>

// Shapes (fixed by the problem)
#define Bb   2
#define SS   1024
#define HH   2048
#define NHH  32
#define NKVV 8
#define DD   64
#define IIF  8192
#define TOK  (Bb*SS)          // 2048 tokens
#define LCK  3

// ================= PTX helpers (arch-neutral: sm_80+ instructions only) ======
__device__ __forceinline__ uint32_t smem_to_u32(const void* p) {
    uint32_t a;
    asm("{ .reg .u64 t; cvta.to.shared.u64 t, %1; cvt.u32.u64 %0, t; }" : "=r"(a) : "l"(p));
    return a;
}

__device__ __forceinline__ void cp16(uint32_t s, const void* g) {
    asm volatile("cp.async.cg.shared.global [%0], [%1], 16;" :: "r"(s), "l"(g) : "memory");
}
#define CP_COMMIT() asm volatile("cp.async.commit_group;" ::: "memory")
#define CP_WAIT(n)  asm volatile("cp.async.wait_group %0;" :: "n"(n) : "memory")

__device__ __forceinline__ void ldsm4(uint32_t* r, uint32_t addr) {
    asm volatile("ldmatrix.sync.aligned.m8n8.x4.shared.b16 {%0,%1,%2,%3}, [%4];"
                 : "=r"(r[0]), "=r"(r[1]), "=r"(r[2]), "=r"(r[3]) : "r"(addr));
}

#define MMA_BF16(c, a, b0, b1)                                            \
    asm volatile("mma.sync.aligned.m16n8k16.row.col.f32.bf16.bf16.f32 "   \
        "{%0,%1,%2,%3}, {%4,%5,%6,%7}, {%8,%9}, {%0,%1,%2,%3};"           \
        : "+f"((c)[0]), "+f"((c)[1]), "+f"((c)[2]), "+f"((c)[3])          \
        : "r"((a)[0]), "r"((a)[1]), "r"((a)[2]), "r"((a)[3]),             \
          "r"(b0), "r"(b1))

// ================= scratch (device globals) =================
__device__ __nv_bfloat16 g_xhi[TOK * 4096],   g_xlo[TOK * 4096];
__device__ __nv_bfloat16 g_wqkv_hi[3072 * 4096],  g_wqkv_lo[3072 * 4096];
__device__ __nv_bfloat16 g_wo_hi[2048 * 2048],    g_wo_lo[2048 * 2048];
__device__ __nv_bfloat16 g_wgu_hi[16384 * 2048],  g_wgu_lo[16384 * 2048];
__device__ __nv_bfloat16 g_wdn_hi[2048 * 8192],   g_wdn_lo[2048 * 8192];
__device__ __nv_bfloat16 g_ahi[TOK * 2048],   g_alo[TOK * 2048];   // attention out
__device__ __nv_bfloat16 g_hnhi[TOK * 2048],  g_hnlo[TOK * 2048];
__device__ __nv_bfloat16 g_acthi[TOK * 8192], g_actlo[TOK * 8192];
__device__ float g_qkv[TOK * 3072];
__device__ float g_q[Bb * NHH * SS * DD];
__device__ float g_k[Bb * NKVV * SS * DD];
__device__ float g_v[Bb * NKVV * SS * DD];
__device__ float g_h2[TOK * 2048];
__device__ float g_gu[TOK * 16384];

__device__ __forceinline__ void split2(float x, __nv_bfloat16& h, __nv_bfloat16& l) {
    h = __float2bfloat16(x);
    l = __float2bfloat16(x - __bfloat162float(h));
}

// ================= tensor-core GEMM (mma.sync bf16, 3-pass split) ============
// C[M,N] = A[M,K] * B[N,K]^T (+resid).  Tile 128x128, BK=32, 256 threads.
// 2-stage cp.async pipeline, 80KB smem -> 2 CTAs/SM for latency hiding.
#define ROWB       80
#define MAT_BYTES  (128 * ROWB)
#define STG_BYTES  (4 * MAT_BYTES)       // 40960 (Ah | Al | Bh | Bl)
#define GEMM_DSMEM (2 * STG_BYTES)       // 81920

__device__ __forceinline__ void stage_mat(uint32_t smat, const __nv_bfloat16* __restrict__ src,
                                          int row0, int K, int k0, int tid) {
#pragma unroll
    for (int h = 0; h < 2; h++) {
        int idx = tid + h * 256;
        int row = idx >> 2, c = idx & 3;
        cp16(smat + row * ROWB + c * 16,
             src + (size_t)(row0 + row) * K + k0 + c * 8);
    }
}

__global__ __launch_bounds__(256, 2) void gemm_mma(
    const __nv_bfloat16* __restrict__ Ahi, const __nv_bfloat16* __restrict__ Alo,
    const __nv_bfloat16* __restrict__ Bhi, const __nv_bfloat16* __restrict__ Blo,
    const float* __restrict__ resid, float* __restrict__ C,
    int ldc, int K, int addResid)
{
    extern __shared__ char dsm[];
    uint32_t sbase = smem_to_u32(dsm);
    int tid = threadIdx.x, wid = tid >> 5, lane = tid & 31;
    int m0 = blockIdx.y * 128, n0 = blockIdx.x * 128;
    int wm = (wid & 1) * 64;
    int wn = (wid >> 1) * 32;
    int tile = lane >> 3, r = lane & 7;

    float acc[4][4][4];
#pragma unroll
    for (int f = 0; f < 4; f++)
#pragma unroll
        for (int n = 0; n < 4; n++)
#pragma unroll
            for (int e = 0; e < 4; e++) acc[f][n][e] = 0.f;

    int nK = K >> 5;
    // prologue: stage 0
    {
        stage_mat(sbase,                 Ahi, m0, K, 0, tid);
        stage_mat(sbase + MAT_BYTES,     Alo, m0, K, 0, tid);
        stage_mat(sbase + 2 * MAT_BYTES, Bhi, n0, K, 0, tid);
        stage_mat(sbase + 3 * MAT_BYTES, Blo, n0, K, 0, tid);
        CP_COMMIT();
    }

    uint32_t aoff = (uint32_t)((((tile & 1) << 3) + r) * ROWB + ((tile >> 1) << 4));
    uint32_t boff = (uint32_t)((((tile >> 1) << 3) + r) * ROWB + ((tile & 1) << 4));

    for (int ks = 0; ks < nK; ks++) {
        int nxt = ks + 1;
        if (nxt < nK) {
            uint32_t sp = sbase + (nxt & 1) * STG_BYTES;
            int k0 = nxt << 5;
            stage_mat(sp,                 Ahi, m0, K, k0, tid);
            stage_mat(sp + MAT_BYTES,     Alo, m0, K, k0, tid);
            stage_mat(sp + 2 * MAT_BYTES, Bhi, n0, K, k0, tid);
            stage_mat(sp + 3 * MAT_BYTES, Blo, n0, K, k0, tid);
            CP_COMMIT();
            CP_WAIT(1);
        } else {
            CP_WAIT(0);
        }
        __syncthreads();

        uint32_t so = sbase + (ks & 1) * STG_BYTES;
        uint32_t aHb = so + (uint32_t)(wm * ROWB);
        uint32_t aLb = aHb + MAT_BYTES;
        uint32_t bHb = so + 2 * MAT_BYTES + (uint32_t)(wn * ROWB);
        uint32_t bLb = bHb + MAT_BYTES;

#pragma unroll
        for (int kk = 0; kk < 2; kk++) {
            uint32_t Ah[4][4], Al[4][4], Bh[2][4], Bl[2][4];
            uint32_t kadd = (uint32_t)(kk << 5);
#pragma unroll
            for (int f = 0; f < 4; f++) {
                uint32_t off = aoff + (uint32_t)(f * 16 * ROWB) + kadd;
                ldsm4(Ah[f], aHb + off);
                ldsm4(Al[f], aLb + off);
            }
#pragma unroll
            for (int g = 0; g < 2; g++) {
                uint32_t off = boff + (uint32_t)(g * 16 * ROWB) + kadd;
                ldsm4(Bh[g], bHb + off);
                ldsm4(Bl[g], bLb + off);
            }
#pragma unroll
            for (int f = 0; f < 4; f++) {
#pragma unroll
                for (int n = 0; n < 4; n++) {
                    const uint32_t* bh = &Bh[n >> 1][(n & 1) * 2];
                    const uint32_t* bl = &Bl[n >> 1][(n & 1) * 2];
                    MMA_BF16(acc[f][n], Ah[f], bh[0], bh[1]);
                    MMA_BF16(acc[f][n], Ah[f], bl[0], bl[1]);
                    MMA_BF16(acc[f][n], Al[f], bh[0], bh[1]);
                }
            }
        }
        __syncthreads();
    }

    int rr = lane >> 2, cc = (lane & 3) * 2;
#pragma unroll
    for (int f = 0; f < 4; f++) {
#pragma unroll
        for (int n = 0; n < 4; n++) {
            int m = m0 + wm + f * 16 + rr;
            int c = n0 + wn + n * 8 + cc;
            size_t i0 = (size_t)m * ldc + c;
            size_t i1 = (size_t)(m + 8) * ldc + c;
            float2 v0 = make_float2(acc[f][n][0], acc[f][n][1]);
            float2 v1 = make_float2(acc[f][n][2], acc[f][n][3]);
            if (addResid) {
                float2 r0 = *(const float2*)(resid + i0);
                float2 r1 = *(const float2*)(resid + i1);
                v0.x += r0.x; v0.y += r0.y;
                v1.x += r1.x; v1.y += r1.y;
            }
            *(float2*)(C + i0) = v0;
            *(float2*)(C + i1) = v1;
        }
    }
}

// ================= small kernels =================
__device__ __forceinline__ float blockReduceSum(float v) {
    __shared__ float red[8];
    int lane = threadIdx.x & 31, w = threadIdx.x >> 5;
#pragma unroll
    for (int o = 16; o; o >>= 1) v += __shfl_xor_sync(0xffffffffu, v, o);
    if (lane == 0) red[w] = v;
    __syncthreads();
    if (w == 0) {
        float t = (lane < 8) ? red[lane] : 0.0f;
#pragma unroll
        for (int o = 4; o; o >>= 1) t += __shfl_xor_sync(0xffffffffu, t, o);
        if (lane == 0) red[0] = t;
    }
    __syncthreads();
    float r = red[0];
    __syncthreads();
    return r;
}

__global__ __launch_bounds__(256) void rmsnorm_concat_kernel(
    const float* __restrict__ emb, const float* __restrict__ hid,
    const float* __restrict__ w_e, const float* __restrict__ w_h,
    __nv_bfloat16* __restrict__ xhi, __nv_bfloat16* __restrict__ xlo)
{
    int t = blockIdx.x;
    const float* e  = emb + (size_t)t * HH;
    const float* hh = hid + (size_t)t * HH;
    float se = 0.f, sh = 0.f;
    for (int i = threadIdx.x; i < HH; i += 256) {
        float a = e[i];  se += a * a;
        float c = hh[i]; sh += c * c;
    }
    se = blockReduceSum(se);
    sh = blockReduceSum(sh);
    float re = rsqrtf(se / (float)HH + 1e-6f);
    float rh = rsqrtf(sh / (float)HH + 1e-6f);
    size_t ro = (size_t)t * 4096;
    for (int i = threadIdx.x; i < HH; i += 256) {
        __nv_bfloat16 hv, lv;
        split2(w_e[i] * e[i] * re, hv, lv);
        xhi[ro + i] = hv; xlo[ro + i] = lv;
        split2(w_h[i] * hh[i] * rh, hv, lv);
        xhi[ro + HH + i] = hv; xlo[ro + HH + i] = lv;
    }
}

__global__ __launch_bounds__(256) void rmsnorm_split_kernel(
    const float* __restrict__ in, const float* __restrict__ w,
    __nv_bfloat16* __restrict__ ohi, __nv_bfloat16* __restrict__ olo)
{
    int t = blockIdx.x;
    const float* r = in + (size_t)t * HH;
    float s = 0.f;
    for (int i = threadIdx.x; i < HH; i += 256) { float a = r[i]; s += a * a; }
    s = blockReduceSum(s);
    float inv = rsqrtf(s / (float)HH + 1e-6f);
    size_t ro = (size_t)t * HH;
    for (int i = threadIdx.x; i < HH; i += 256) {
        __nv_bfloat16 hv, lv;
        split2(w[i] * r[i] * inv, hv, lv);
        ohi[ro + i] = hv; olo[ro + i] = lv;
    }
}

__global__ __launch_bounds__(256) void convert_split_kernel(
    const float* __restrict__ src, __nv_bfloat16* __restrict__ hi,
    __nv_bfloat16* __restrict__ lo, int n)
{
    int i = (blockIdx.x * 256 + threadIdx.x) * 4;
    if (i < n) {
        float4 v = *(const float4*)(src + i);
        __nv_bfloat16 h0, l0, h1, l1, h2, l2, h3, l3;
        split2(v.x, h0, l0); split2(v.y, h1, l1);
        split2(v.z, h2, l2); split2(v.w, h3, l3);
        __nv_bfloat162* ph = (__nv_bfloat162*)(hi + i);
        __nv_bfloat162* pl = (__nv_bfloat162*)(lo + i);
        ph[0] = __nv_bfloat162(h0, h1); ph[1] = __nv_bfloat162(h2, h3);
        pl[0] = __nv_bfloat162(l0, l1); pl[1] = __nv_bfloat162(l2, l3);
    }
}

// RoPE + layout transform
__global__ __launch_bounds__(256) void rope_kernel(
    const float* __restrict__ qkv, const int* __restrict__ pos_ids,
    float* __restrict__ q, float* __restrict__ k, float* __restrict__ v)
{
    int t = blockIdx.x;
    int b = t >> 10, s = t & 1023;
    float pos = (float)(pos_ids[t] + LCK);
    const float* row = qkv + (size_t)t * 3072;
    const float lg = logf(10000.0f) / 32.0f;

    for (int p = threadIdx.x; p < 1024 + 256; p += 256) {
        const float* src; float* dst; int hh, d;
        if (p < 1024) {
            hh = p >> 5; d = p & 31;
            src = row + hh * 64;
            dst = q + (((size_t)b * NHH + hh) * SS + s) * 64;
        } else {
            int pp = p - 1024;
            hh = pp >> 5; d = pp & 31;
            src = row + 2048 + hh * 64;
            dst = k + (((size_t)b * NKVV + hh) * SS + s) * 64;
        }
        float invf = expf(-(float)d * lg);
        float ang = pos * invf;
        float c = cosf(ang), sn = sinf(ang);
        float x0 = src[d], x1 = src[d + 32];
        dst[d]      = x0 * c - x1 * sn;
        dst[d + 32] = x1 * c + x0 * sn;
    }
    for (int p = threadIdx.x; p < 512; p += 256) {
        int hh = p >> 6, d = p & 63;
        v[(((size_t)b * NKVV + hh) * SS + s) * 64 + d] = row[2560 + p];
    }
}

// attention (flash-style, fp32, no online-max; forced 3 CTAs/SM)
__global__ __launch_bounds__(256, 3) void attn_kernel(
    const float* __restrict__ q, const float* __restrict__ cache_k,
    const float* __restrict__ cache_v, const float* __restrict__ kcur,
    const float* __restrict__ vcur,
    __nv_bfloat16* __restrict__ ohi, __nv_bfloat16* __restrict__ olo)
{
    extern __shared__ float sm[];
    float (*Qs)[68] = (float (*)[68])sm;
    float (*Ks)[68] = (float (*)[68])(sm + 64 * 68);
    float (*Vs)[68] = (float (*)[68])(sm + 2 * 64 * 68);
    float (*sc)[68] = (float (*)[68])(sm + 3 * 64 * 68);
    float* l_s = sm + 4 * 64 * 68;

    int tid = threadIdx.x;
    int tx = tid & 15, ty = tid >> 4;
    int lr = tid >> 2, lc = (tid & 3) << 2;
    int qt = blockIdx.x, h = blockIdx.y, b = blockIdx.z;
    int q0 = qt * 64;
    size_t bh = (size_t)b * NHH + h;
    const float scale = 0.125f;

    {
        const float* qb = q + (bh * SS + q0 + lr) * 64;
#pragma unroll
        for (int dblk = 0; dblk < 4; dblk++) {
            int d = lc + dblk * 16;
            float4 t4 = *(const float4*)(qb + d);
            Qs[d + 0][lr] = t4.x; Qs[d + 1][lr] = t4.y;
            Qs[d + 2][lr] = t4.z; Qs[d + 3][lr] = t4.w;
        }
    }
    if (tid < 64) l_s[tid] = 0.f;

    float acc[4][4];
#pragma unroll
    for (int i = 0; i < 4; i++)
#pragma unroll
        for (int j = 0; j < 4; j++) acc[i][j] = 0.f;

    const float* k0p = cache_k + bh * SS * 64;
    const float* v0p = cache_v + bh * SS * 64;

    for (int kb = 0; kb <= qt; kb++) {
        __syncthreads();
        {
            const float* kp = k0p + (size_t)(kb * 64 + lr) * 64;
            const float* vp = v0p + (size_t)(kb * 64 + lr) * 64;
#pragma unroll
            for (int dblk = 0; dblk < 4; dblk++) {
                int d = lc + dblk * 16;
                float4 k4 = *(const float4*)(kp + d);
                Ks[d + 0][lr] = k4.x; Ks[d + 1][lr] = k4.y;
                Ks[d + 2][lr] = k4.z; Ks[d + 3][lr] = k4.w;
                float4 v4 = *(const float4*)(vp + d);
                *(float4*)&Vs[lr][d] = v4;
            }
        }
        __syncthreads();

        float sreg[4][4];
#pragma unroll
        for (int i = 0; i < 4; i++)
#pragma unroll
            for (int j = 0; j < 4; j++) sreg[i][j] = 0.f;
#pragma unroll 4
        for (int dk = 0; dk < 64; dk++) {
            float4 qa = *(const float4*)&Qs[dk][ty * 4];
            float4 ka = *(const float4*)&Ks[dk][tx * 4];
            float qf[4] = {qa.x, qa.y, qa.z, qa.w};
            float kf[4] = {ka.x, ka.y, ka.z, ka.w};
#pragma unroll
            for (int i = 0; i < 4; i++)
#pragma unroll
                for (int j = 0; j < 4; j++)
                    sreg[i][j] += qf[i] * kf[j];
        }
        // scale + mask + exp + row partial sums, write P
        bool diag = (kb == qt);
        float rs[4];
#pragma unroll
        for (int i = 0; i < 4; i++) {
            rs[i] = 0.f;
#pragma unroll
            for (int j = 0; j < 4; j++) {
                float vv = sreg[i][j] * scale;
                if (diag && (tx * 4 + j) > (ty * 4 + i)) vv = -1e30f;
                vv = __expf(vv);
                sreg[i][j] = vv;
                rs[i] += vv;
            }
            float4 st; st.x = sreg[i][0]; st.y = sreg[i][1]; st.z = sreg[i][2]; st.w = sreg[i][3];
            *(float4*)&sc[ty * 4 + i][tx * 4] = st;
        }
        // reduce row sums across the 16 tx-lanes (lane bits 0..3)
#pragma unroll
        for (int i = 0; i < 4; i++) {
            rs[i] += __shfl_xor_sync(0xffffffffu, rs[i], 1);
            rs[i] += __shfl_xor_sync(0xffffffffu, rs[i], 2);
            rs[i] += __shfl_xor_sync(0xffffffffu, rs[i], 4);
            rs[i] += __shfl_xor_sync(0xffffffffu, rs[i], 8);
        }
        if (tx == 0) {
#pragma unroll
            for (int i = 0; i < 4; i++) l_s[ty * 4 + i] += rs[i];
        }
        __syncthreads();

        // O += P V (no rescale needed)
#pragma unroll 2
        for (int j = 0; j < 64; j++) {
            float4 vv = *(const float4*)&Vs[j][tx * 4];
            float vf[4] = {vv.x, vv.y, vv.z, vv.w};
#pragma unroll
            for (int i = 0; i < 4; i++) {
                float p = sc[ty * 4 + i][j];
#pragma unroll
                for (int jj = 0; jj < 4; jj++) acc[i][jj] += p * vf[jj];
            }
        }
    }

    // ---- 3 extra (diagonal) keys: cache_k[1], cache_k[2], current k ----
    __syncthreads();
    {
        int rr = lr, lane = tid & 3;
        if (lane < 3) {
            int s = q0 + rr;
            const float* kvec;
            if (lane < 2)
                kvec = cache_k + (((size_t)(1 + lane) * Bb * NHH + bh) * SS + s) * 64;
            else
                kvec = kcur + (((size_t)b * NKVV + (h >> 2)) * SS + s) * 64;
            float dot = 0.f;
#pragma unroll 8
            for (int d = 0; d < 64; d++) dot += Qs[d][rr] * kvec[d];
            sc[rr][lane] = __expf(dot * scale);
        }
    }
    __syncthreads();
    if (tx == 0) {
#pragma unroll
        for (int i = 0; i < 4; i++) {
            int rr2 = ty * 4 + i;
            l_s[rr2] += sc[rr2][0] + sc[rr2][1] + sc[rr2][2];
        }
    }
    __syncthreads();
#pragma unroll
    for (int i = 0; i < 4; i++) {
        int s = q0 + ty * 4 + i;
#pragma unroll
        for (int n = 0; n < 3; n++) {
            const float* vvec = (n < 2)
                ? cache_v + (((size_t)(1 + n) * Bb * NHH + bh) * SS + s) * 64
                : vcur + (((size_t)b * NKVV + (h >> 2)) * SS + s) * 64;
            float p = sc[ty * 4 + i][n];
            float4 vv = *(const float4*)(vvec + tx * 4);
            acc[i][0] += p * vv.x; acc[i][1] += p * vv.y;
            acc[i][2] += p * vv.z; acc[i][3] += p * vv.w;
        }
    }
#pragma unroll
    for (int i = 0; i < 4; i++) {
        int s = q0 + ty * 4 + i;
        float inv = 1.0f / l_s[ty * 4 + i];
        size_t oidx = ((size_t)(b * SS + s)) * HH + h * 64 + tx * 4;
#pragma unroll
        for (int j = 0; j < 4; j++) {
            __nv_bfloat16 hv, lv;
            split2(acc[i][j] * inv, hv, lv);
            ohi[oidx + j] = hv;
            olo[oidx + j] = lv;
        }
    }
}

// SiLU(gate)*up -> split bf16 pair
__global__ __launch_bounds__(256) void silu_split_kernel(
    const float* __restrict__ gu, __nv_bfloat16* __restrict__ hi,
    __nv_bfloat16* __restrict__ lo)
{
    int i = blockIdx.x * 256 + threadIdx.x;
    int row = i >> 13, col = i & 8191;
    float g = gu[(size_t)row * 16384 + col];
    float u = gu[(size_t)row * 16384 + 8192 + col];
    float a = g / (1.0f + expf(-g)) * u;
    __nv_bfloat16 hv, lv;
    split2(a, hv, lv);
    hi[i] = hv; lo[i] = lv;
}

// ================= launcher =================
extern "C" void kernel_launch(void* const* d_in, const int* in_sizes, int n_in,
                              void* d_out, int out_size)
{
    const float* input_emb     = (const float*)d_in[0];
    const float* hidden_states = (const float*)d_in[1];
    const float* cache_k       = (const float*)d_in[2];
    const float* cache_v       = (const float*)d_in[3];
    const int*   position_ids  = (const int*)d_in[5];
    const float* wq            = (const float*)d_in[6];
    const float* wk            = (const float*)d_in[7];
    const float* wv            = (const float*)d_in[8];
    const float* wo            = (const float*)d_in[9];
    const float* w_gate        = (const float*)d_in[10];
    const float* w_up          = (const float*)d_in[11];
    const float* w_down        = (const float*)d_in[12];
    const float* hidden_norm_w = (const float*)d_in[13];
    const float* input_ln_w    = (const float*)d_in[14];
    const float* post_ln_w     = (const float*)d_in[15];
    float* out = (float*)d_out;

    __nv_bfloat16 *xhi, *xlo, *wqkvh, *wqkvl, *woh, *wol, *wguh, *wgul, *wdnh, *wdnl;
    __nv_bfloat16 *ahi, *alo, *hnhi, *hnlo, *acth, *actl;
    float *qkv, *q, *k, *v, *h2, *gu;
    cudaGetSymbolAddress((void**)&xhi, g_xhi);     cudaGetSymbolAddress((void**)&xlo, g_xlo);
    cudaGetSymbolAddress((void**)&wqkvh, g_wqkv_hi); cudaGetSymbolAddress((void**)&wqkvl, g_wqkv_lo);
    cudaGetSymbolAddress((void**)&woh, g_wo_hi);   cudaGetSymbolAddress((void**)&wol, g_wo_lo);
    cudaGetSymbolAddress((void**)&wguh, g_wgu_hi); cudaGetSymbolAddress((void**)&wgul, g_wgu_lo);
    cudaGetSymbolAddress((void**)&wdnh, g_wdn_hi); cudaGetSymbolAddress((void**)&wdnl, g_wdn_lo);
    cudaGetSymbolAddress((void**)&ahi, g_ahi);     cudaGetSymbolAddress((void**)&alo, g_alo);
    cudaGetSymbolAddress((void**)&hnhi, g_hnhi);   cudaGetSymbolAddress((void**)&hnlo, g_hnlo);
    cudaGetSymbolAddress((void**)&acth, g_acthi);  cudaGetSymbolAddress((void**)&actl, g_actlo);
    cudaGetSymbolAddress((void**)&qkv, g_qkv);
    cudaGetSymbolAddress((void**)&q, g_q);
    cudaGetSymbolAddress((void**)&k, g_k);
    cudaGetSymbolAddress((void**)&v, g_v);
    cudaGetSymbolAddress((void**)&h2, g_h2);
    cudaGetSymbolAddress((void**)&gu, g_gu);

    cudaFuncSetAttribute(gemm_mma, cudaFuncAttributeMaxDynamicSharedMemorySize, GEMM_DSMEM);
    const int attn_smem = (4 * 64 * 68 + 64) * (int)sizeof(float);
    cudaFuncSetAttribute(attn_kernel, cudaFuncAttributeMaxDynamicSharedMemorySize, attn_smem);

    // weight conversions (fp32 -> bf16 hi/lo), packed QKV and gate|up
    convert_split_kernel<<<2048 * 4096 / 1024, 256>>>(wq, wqkvh, wqkvl, 2048 * 4096);
    convert_split_kernel<<<512 * 4096 / 1024, 256>>>(wk, wqkvh + 2048 * 4096, wqkvl + 2048 * 4096, 512 * 4096);
    convert_split_kernel<<<512 * 4096 / 1024, 256>>>(wv, wqkvh + 2560 * 4096, wqkvl + 2560 * 4096, 512 * 4096);
    convert_split_kernel<<<2048 * 2048 / 1024, 256>>>(wo, woh, wol, 2048 * 2048);
    convert_split_kernel<<<8192 * 2048 / 1024, 256>>>(w_gate, wguh, wgul, 8192 * 2048);
    convert_split_kernel<<<8192 * 2048 / 1024, 256>>>(w_up, wguh + 8192 * 2048, wgul + 8192 * 2048, 8192 * 2048);
    convert_split_kernel<<<2048 * 8192 / 1024, 256>>>(w_down, wdnh, wdnl, 2048 * 8192);

    // 1. norms + concat (split bf16)
    rmsnorm_concat_kernel<<<TOK, 256>>>(input_emb, hidden_states, input_ln_w, hidden_norm_w, xhi, xlo);
    // 2. QKV GEMM (packed, N=3072)
    gemm_mma<<<dim3(3072 / 128, TOK / 128), 256, GEMM_DSMEM>>>(xhi, xlo, wqkvh, wqkvl, nullptr, qkv, 3072, 4096, 0);
    // 3. RoPE + reshape
    rope_kernel<<<TOK, 256>>>(qkv, position_ids, q, k, v);
    // 4. attention -> split bf16
    attn_kernel<<<dim3(SS / 64, NHH, Bb), 256, attn_smem>>>(q, cache_k, cache_v, k, v, ahi, alo);
    // 5. out projection + residual
    gemm_mma<<<dim3(2048 / 128, TOK / 128), 256, GEMM_DSMEM>>>(ahi, alo, woh, wol, hidden_states, h2, 2048, 2048, 1);
    // 6. post-attn norm -> split bf16
    rmsnorm_split_kernel<<<TOK, 256>>>(h2, post_ln_w, hnhi, hnlo);
    // 7. gate|up GEMM (packed, N=16384)
    gemm_mma<<<dim3(16384 / 128, TOK / 128), 256, GEMM_DSMEM>>>(hnhi, hnlo, wguh, wgul, nullptr, gu, 16384, 2048, 0);
    // 8. SiLU * up -> split bf16
    silu_split_kernel<<<TOK * IIF / 256, 256>>>(gu, acth, actl);
    // 9. down projection + residual -> final output
    gemm_mma<<<dim3(2048 / 128, TOK / 128), 256, GEMM_DSMEM>>>(acth, actl, wdnh, wdnl, h2, out, 2048, 8192, 1);

    (void)in_sizes; (void)n_in; (void)out_size;
}

// round 14
// speedup vs baseline: 1.1216x; 1.0003x over previous
#include <cuda_runtime.h>
#include <cuda_bf16.h>
#include <cstdint>
#include <math.h>

// Shapes (fixed by the problem)
#define Bb   2
#define SS   1024
#define HH   2048
#define NHH  32
#define NKVV 8
#define DD   64
#define IIF  8192
#define TOK  (Bb*SS)          // 2048 tokens
#define LCK  3

// ================= PTX helpers (arch-neutral: sm_80+ instructions only) ======
__device__ __forceinline__ uint32_t smem_to_u32(const void* p) {
    uint32_t a;
    asm("{ .reg .u64 t; cvta.to.shared.u64 t, %1; cvt.u32.u64 %0, t; }" : "=r"(a) : "l"(p));
    return a;
}

__device__ __forceinline__ void cp16(uint32_t s, const void* g) {
    asm volatile("cp.async.cg.shared.global [%0], [%1], 16;" :: "r"(s), "l"(g) : "memory");
}
#define CP_COMMIT() asm volatile("cp.async.commit_group;" ::: "memory")
#define CP_WAIT(n)  asm volatile("cp.async.wait_group %0;" :: "n"(n) : "memory")

__device__ __forceinline__ void ldsm4(uint32_t* r, uint32_t addr) {
    asm volatile("ldmatrix.sync.aligned.m8n8.x4.shared.b16 {%0,%1,%2,%3}, [%4];"
                 : "=r"(r[0]), "=r"(r[1]), "=r"(r[2]), "=r"(r[3]) : "r"(addr));
}

#define MMA_BF16(c, a, b0, b1)                                            \
    asm volatile("mma.sync.aligned.m16n8k16.row.col.f32.bf16.bf16.f32 "   \
        "{%0,%1,%2,%3}, {%4,%5,%6,%7}, {%8,%9}, {%0,%1,%2,%3};"           \
        : "+f"((c)[0]), "+f"((c)[1]), "+f"((c)[2]), "+f"((c)[3])          \
        : "r"((a)[0]), "r"((a)[1]), "r"((a)[2]), "r"((a)[3]),             \
          "r"(b0), "r"(b1))

// ================= scratch (device globals) =================
__device__ __nv_bfloat16 g_xhi[TOK * 4096],   g_xlo[TOK * 4096];
__device__ __nv_bfloat16 g_wqkv_hi[3072 * 4096],  g_wqkv_lo[3072 * 4096];
__device__ __nv_bfloat16 g_wo_hi[2048 * 2048],    g_wo_lo[2048 * 2048];
__device__ __nv_bfloat16 g_wgu_hi[16384 * 2048],  g_wgu_lo[16384 * 2048];
__device__ __nv_bfloat16 g_wdn_hi[2048 * 8192],   g_wdn_lo[2048 * 8192];
__device__ __nv_bfloat16 g_ahi[TOK * 2048],   g_alo[TOK * 2048];   // attention out
__device__ __nv_bfloat16 g_hnhi[TOK * 2048],  g_hnlo[TOK * 2048];
__device__ __nv_bfloat16 g_acthi[TOK * 8192], g_actlo[TOK * 8192];
__device__ float g_qkv[TOK * 3072];
__device__ float g_q[Bb * NHH * SS * DD];
__device__ float g_k[Bb * NKVV * SS * DD];
__device__ float g_v[Bb * NKVV * SS * DD];
__device__ float g_h2[TOK * 2048];
__device__ float g_gu[TOK * 16384];

__device__ __forceinline__ void split2(float x, __nv_bfloat16& h, __nv_bfloat16& l) {
    h = __float2bfloat16(x);
    l = __float2bfloat16(x - __bfloat162float(h));
}

// ================= tensor-core GEMM (mma.sync bf16, 3-pass split) ============
// C[M,N] = A[M,K] * B[N,K]^T (+resid).  Tile 128x128, BK=32, 256 threads.
// 2-stage cp.async pipeline, 80KB smem -> 2 CTAs/SM for latency hiding.
#define ROWB       80
#define MAT_BYTES  (128 * ROWB)
#define STG_BYTES  (4 * MAT_BYTES)       // 40960 (Ah | Al | Bh | Bl)
#define GEMM_DSMEM (2 * STG_BYTES)       // 81920

__device__ __forceinline__ void stage_mat(uint32_t smat, const __nv_bfloat16* __restrict__ src,
                                          int row0, int K, int k0, int tid) {
#pragma unroll
    for (int h = 0; h < 2; h++) {
        int idx = tid + h * 256;
        int row = idx >> 2, c = idx & 3;
        cp16(smat + row * ROWB + c * 16,
             src + (size_t)(row0 + row) * K + k0 + c * 8);
    }
}

__global__ __launch_bounds__(256, 2) void gemm_mma(
    const __nv_bfloat16* __restrict__ Ahi, const __nv_bfloat16* __restrict__ Alo,
    const __nv_bfloat16* __restrict__ Bhi, const __nv_bfloat16* __restrict__ Blo,
    const float* __restrict__ resid, float* __restrict__ C,
    int ldc, int K, int addResid)
{
    extern __shared__ char dsm[];
    uint32_t sbase = smem_to_u32(dsm);
    int tid = threadIdx.x, wid = tid >> 5, lane = tid & 31;
    int m0 = blockIdx.y * 128, n0 = blockIdx.x * 128;
    int wm = (wid & 1) * 64;
    int wn = (wid >> 1) * 32;
    int tile = lane >> 3, r = lane & 7;

    float acc[4][4][4];
#pragma unroll
    for (int f = 0; f < 4; f++)
#pragma unroll
        for (int n = 0; n < 4; n++)
#pragma unroll
            for (int e = 0; e < 4; e++) acc[f][n][e] = 0.f;

    int nK = K >> 5;
    // prologue: stage 0
    {
        stage_mat(sbase,                 Ahi, m0, K, 0, tid);
        stage_mat(sbase + MAT_BYTES,     Alo, m0, K, 0, tid);
        stage_mat(sbase + 2 * MAT_BYTES, Bhi, n0, K, 0, tid);
        stage_mat(sbase + 3 * MAT_BYTES, Blo, n0, K, 0, tid);
        CP_COMMIT();
    }

    uint32_t aoff = (uint32_t)((((tile & 1) << 3) + r) * ROWB + ((tile >> 1) << 4));
    uint32_t boff = (uint32_t)((((tile >> 1) << 3) + r) * ROWB + ((tile & 1) << 4));

    for (int ks = 0; ks < nK; ks++) {
        int nxt = ks + 1;
        if (nxt < nK) {
            uint32_t sp = sbase + (nxt & 1) * STG_BYTES;
            int k0 = nxt << 5;
            stage_mat(sp,                 Ahi, m0, K, k0, tid);
            stage_mat(sp + MAT_BYTES,     Alo, m0, K, k0, tid);
            stage_mat(sp + 2 * MAT_BYTES, Bhi, n0, K, k0, tid);
            stage_mat(sp + 3 * MAT_BYTES, Blo, n0, K, k0, tid);
            CP_COMMIT();
            CP_WAIT(1);
        } else {
            CP_WAIT(0);
        }
        __syncthreads();

        uint32_t so = sbase + (ks & 1) * STG_BYTES;
        uint32_t aHb = so + (uint32_t)(wm * ROWB);
        uint32_t aLb = aHb + MAT_BYTES;
        uint32_t bHb = so + 2 * MAT_BYTES + (uint32_t)(wn * ROWB);
        uint32_t bLb = bHb + MAT_BYTES;

#pragma unroll
        for (int kk = 0; kk < 2; kk++) {
            uint32_t Ah[4][4], Al[4][4], Bh[2][4], Bl[2][4];
            uint32_t kadd = (uint32_t)(kk << 5);
#pragma unroll
            for (int f = 0; f < 4; f++) {
                uint32_t off = aoff + (uint32_t)(f * 16 * ROWB) + kadd;
                ldsm4(Ah[f], aHb + off);
                ldsm4(Al[f], aLb + off);
            }
#pragma unroll
            for (int g = 0; g < 2; g++) {
                uint32_t off = boff + (uint32_t)(g * 16 * ROWB) + kadd;
                ldsm4(Bh[g], bHb + off);
                ldsm4(Bl[g], bLb + off);
            }
#pragma unroll
            for (int f = 0; f < 4; f++) {
#pragma unroll
                for (int n = 0; n < 4; n++) {
                    const uint32_t* bh = &Bh[n >> 1][(n & 1) * 2];
                    const uint32_t* bl = &Bl[n >> 1][(n & 1) * 2];
                    MMA_BF16(acc[f][n], Ah[f], bh[0], bh[1]);
                    MMA_BF16(acc[f][n], Ah[f], bl[0], bl[1]);
                    MMA_BF16(acc[f][n], Al[f], bh[0], bh[1]);
                }
            }
        }
        __syncthreads();
    }

    int rr = lane >> 2, cc = (lane & 3) * 2;
#pragma unroll
    for (int f = 0; f < 4; f++) {
#pragma unroll
        for (int n = 0; n < 4; n++) {
            int m = m0 + wm + f * 16 + rr;
            int c = n0 + wn + n * 8 + cc;
            size_t i0 = (size_t)m * ldc + c;
            size_t i1 = (size_t)(m + 8) * ldc + c;
            float2 v0 = make_float2(acc[f][n][0], acc[f][n][1]);
            float2 v1 = make_float2(acc[f][n][2], acc[f][n][3]);
            if (addResid) {
                float2 r0 = *(const float2*)(resid + i0);
                float2 r1 = *(const float2*)(resid + i1);
                v0.x += r0.x; v0.y += r0.y;
                v1.x += r1.x; v1.y += r1.y;
            }
            *(float2*)(C + i0) = v0;
            *(float2*)(C + i1) = v1;
        }
    }
}

// ================= small kernels =================
__device__ __forceinline__ float blockReduceSum(float v) {
    __shared__ float red[8];
    int lane = threadIdx.x & 31, w = threadIdx.x >> 5;
#pragma unroll
    for (int o = 16; o; o >>= 1) v += __shfl_xor_sync(0xffffffffu, v, o);
    if (lane == 0) red[w] = v;
    __syncthreads();
    if (w == 0) {
        float t = (lane < 8) ? red[lane] : 0.0f;
#pragma unroll
        for (int o = 4; o; o >>= 1) t += __shfl_xor_sync(0xffffffffu, t, o);
        if (lane == 0) red[0] = t;
    }
    __syncthreads();
    float r = red[0];
    __syncthreads();
    return r;
}

__global__ __launch_bounds__(256) void rmsnorm_concat_kernel(
    const float* __restrict__ emb, const float* __restrict__ hid,
    const float* __restrict__ w_e, const float* __restrict__ w_h,
    __nv_bfloat16* __restrict__ xhi, __nv_bfloat16* __restrict__ xlo)
{
    int t = blockIdx.x;
    const float* e  = emb + (size_t)t * HH;
    const float* hh = hid + (size_t)t * HH;
    float se = 0.f, sh = 0.f;
    for (int i = threadIdx.x; i < HH; i += 256) {
        float a = e[i];  se += a * a;
        float c = hh[i]; sh += c * c;
    }
    se = blockReduceSum(se);
    sh = blockReduceSum(sh);
    float re = rsqrtf(se / (float)HH + 1e-6f);
    float rh = rsqrtf(sh / (float)HH + 1e-6f);
    size_t ro = (size_t)t * 4096;
    for (int i = threadIdx.x; i < HH; i += 256) {
        __nv_bfloat16 hv, lv;
        split2(w_e[i] * e[i] * re, hv, lv);
        xhi[ro + i] = hv; xlo[ro + i] = lv;
        split2(w_h[i] * hh[i] * rh, hv, lv);
        xhi[ro + HH + i] = hv; xlo[ro + HH + i] = lv;
    }
}

__global__ __launch_bounds__(256) void rmsnorm_split_kernel(
    const float* __restrict__ in, const float* __restrict__ w,
    __nv_bfloat16* __restrict__ ohi, __nv_bfloat16* __restrict__ olo)
{
    int t = blockIdx.x;
    const float* r = in + (size_t)t * HH;
    float s = 0.f;
    for (int i = threadIdx.x; i < HH; i += 256) { float a = r[i]; s += a * a; }
    s = blockReduceSum(s);
    float inv = rsqrtf(s / (float)HH + 1e-6f);
    size_t ro = (size_t)t * HH;
    for (int i = threadIdx.x; i < HH; i += 256) {
        __nv_bfloat16 hv, lv;
        split2(w[i] * r[i] * inv, hv, lv);
        ohi[ro + i] = hv; olo[ro + i] = lv;
    }
}

__global__ __launch_bounds__(256) void convert_split_kernel(
    const float* __restrict__ src, __nv_bfloat16* __restrict__ hi,
    __nv_bfloat16* __restrict__ lo, int n)
{
    int i = (blockIdx.x * 256 + threadIdx.x) * 4;
    if (i < n) {
        float4 v = *(const float4*)(src + i);
        __nv_bfloat16 h0, l0, h1, l1, h2, l2, h3, l3;
        split2(v.x, h0, l0); split2(v.y, h1, l1);
        split2(v.z, h2, l2); split2(v.w, h3, l3);
        __nv_bfloat162* ph = (__nv_bfloat162*)(hi + i);
        __nv_bfloat162* pl = (__nv_bfloat162*)(lo + i);
        ph[0] = __nv_bfloat162(h0, h1); ph[1] = __nv_bfloat162(h2, h3);
        pl[0] = __nv_bfloat162(l0, l1); pl[1] = __nv_bfloat162(l2, l3);
    }
}

// combined wq|wk|wv convert into the packed QKV weight buffer (one launch)
__global__ __launch_bounds__(256) void convert_qkv_kernel(
    const float* __restrict__ wq, const float* __restrict__ wk,
    const float* __restrict__ wv, __nv_bfloat16* __restrict__ hi,
    __nv_bfloat16* __restrict__ lo)
{
    int i = (blockIdx.x * 256 + threadIdx.x) * 4;   // over 3072*4096
    int row = i >> 12;
    const float* src;
    if (row < 2048)       src = wq + i;
    else if (row < 2560)  src = wk + (i - 2048 * 4096);
    else                  src = wv + (i - 2560 * 4096);
    float4 v = *(const float4*)src;
    __nv_bfloat16 h0, l0, h1, l1, h2, l2, h3, l3;
    split2(v.x, h0, l0); split2(v.y, h1, l1);
    split2(v.z, h2, l2); split2(v.w, h3, l3);
    __nv_bfloat162* ph = (__nv_bfloat162*)(hi + i);
    __nv_bfloat162* pl = (__nv_bfloat162*)(lo + i);
    ph[0] = __nv_bfloat162(h0, h1); ph[1] = __nv_bfloat162(h2, h3);
    pl[0] = __nv_bfloat162(l0, l1); pl[1] = __nv_bfloat162(l2, l3);
}

// RoPE + layout transform
__global__ __launch_bounds__(256) void rope_kernel(
    const float* __restrict__ qkv, const int* __restrict__ pos_ids,
    float* __restrict__ q, float* __restrict__ k, float* __restrict__ v)
{
    int t = blockIdx.x;
    int b = t >> 10, s = t & 1023;
    float pos = (float)(pos_ids[t] + LCK);
    const float* row = qkv + (size_t)t * 3072;
    const float lg = logf(10000.0f) / 32.0f;

    for (int p = threadIdx.x; p < 1024 + 256; p += 256) {
        const float* src; float* dst; int hh, d;
        if (p < 1024) {
            hh = p >> 5; d = p & 31;
            src = row + hh * 64;
            dst = q + (((size_t)b * NHH + hh) * SS + s) * 64;
        } else {
            int pp = p - 1024;
            hh = pp >> 5; d = pp & 31;
            src = row + 2048 + hh * 64;
            dst = k + (((size_t)b * NKVV + hh) * SS + s) * 64;
        }
        float invf = expf(-(float)d * lg);
        float ang = pos * invf;
        float c = cosf(ang), sn = sinf(ang);
        float x0 = src[d], x1 = src[d + 32];
        dst[d]      = x0 * c - x1 * sn;
        dst[d + 32] = x1 * c + x0 * sn;
    }
    for (int p = threadIdx.x; p < 512; p += 256) {
        int hh = p >> 6, d = p & 63;
        v[(((size_t)b * NKVV + hh) * SS + s) * 64 + d] = row[2560 + p];
    }
}

// attention (flash-style, fp32, no online-max; LPT qt ordering)
__global__ __launch_bounds__(256, 3) void attn_kernel(
    const float* __restrict__ q, const float* __restrict__ cache_k,
    const float* __restrict__ cache_v, const float* __restrict__ kcur,
    const float* __restrict__ vcur,
    __nv_bfloat16* __restrict__ ohi, __nv_bfloat16* __restrict__ olo)
{
    extern __shared__ float sm[];
    float (*Qs)[68] = (float (*)[68])sm;
    float (*Ks)[68] = (float (*)[68])(sm + 64 * 68);
    float (*Vs)[68] = (float (*)[68])(sm + 2 * 64 * 68);
    float (*sc)[68] = (float (*)[68])(sm + 3 * 64 * 68);
    float* l_s = sm + 4 * 64 * 68;

    int tid = threadIdx.x;
    int tx = tid & 15, ty = tid >> 4;
    int lr = tid >> 2, lc = (tid & 3) << 2;
    int qt = gridDim.x - 1 - blockIdx.x;   // LPT: heaviest blocks first
    int h = blockIdx.y, b = blockIdx.z;
    int q0 = qt * 64;
    size_t bh = (size_t)b * NHH + h;
    const float scale = 0.125f;

    {
        const float* qb = q + (bh * SS + q0 + lr) * 64;
#pragma unroll
        for (int dblk = 0; dblk < 4; dblk++) {
            int d = lc + dblk * 16;
            float4 t4 = *(const float4*)(qb + d);
            Qs[d + 0][lr] = t4.x; Qs[d + 1][lr] = t4.y;
            Qs[d + 2][lr] = t4.z; Qs[d + 3][lr] = t4.w;
        }
    }
    if (tid < 64) l_s[tid] = 0.f;

    float acc[4][4];
#pragma unroll
    for (int i = 0; i < 4; i++)
#pragma unroll
        for (int j = 0; j < 4; j++) acc[i][j] = 0.f;

    const float* k0p = cache_k + bh * SS * 64;
    const float* v0p = cache_v + bh * SS * 64;

    for (int kb = 0; kb <= qt; kb++) {
        __syncthreads();
        {
            const float* kp = k0p + (size_t)(kb * 64 + lr) * 64;
            const float* vp = v0p + (size_t)(kb * 64 + lr) * 64;
#pragma unroll
            for (int dblk = 0; dblk < 4; dblk++) {
                int d = lc + dblk * 16;
                float4 k4 = *(const float4*)(kp + d);
                Ks[d + 0][lr] = k4.x; Ks[d + 1][lr] = k4.y;
                Ks[d + 2][lr] = k4.z; Ks[d + 3][lr] = k4.w;
                float4 v4 = *(const float4*)(vp + d);
                *(float4*)&Vs[lr][d] = v4;
            }
        }
        __syncthreads();

        float sreg[4][4];
#pragma unroll
        for (int i = 0; i < 4; i++)
#pragma unroll
            for (int j = 0; j < 4; j++) sreg[i][j] = 0.f;
#pragma unroll 4
        for (int dk = 0; dk < 64; dk++) {
            float4 qa = *(const float4*)&Qs[dk][ty * 4];
            float4 ka = *(const float4*)&Ks[dk][tx * 4];
            float qf[4] = {qa.x, qa.y, qa.z, qa.w};
            float kf[4] = {ka.x, ka.y, ka.z, ka.w};
#pragma unroll
            for (int i = 0; i < 4; i++)
#pragma unroll
                for (int j = 0; j < 4; j++)
                    sreg[i][j] += qf[i] * kf[j];
        }
        // scale + mask + exp + row partial sums, write P
        bool diag = (kb == qt);
        float rs[4];
#pragma unroll
        for (int i = 0; i < 4; i++) {
            rs[i] = 0.f;
#pragma unroll
            for (int j = 0; j < 4; j++) {
                float vv = sreg[i][j] * scale;
                if (diag && (tx * 4 + j) > (ty * 4 + i)) vv = -1e30f;
                vv = __expf(vv);
                sreg[i][j] = vv;
                rs[i] += vv;
            }
            float4 st; st.x = sreg[i][0]; st.y = sreg[i][1]; st.z = sreg[i][2]; st.w = sreg[i][3];
            *(float4*)&sc[ty * 4 + i][tx * 4] = st;
        }
#pragma unroll
        for (int i = 0; i < 4; i++) {
            rs[i] += __shfl_xor_sync(0xffffffffu, rs[i], 1);
            rs[i] += __shfl_xor_sync(0xffffffffu, rs[i], 2);
            rs[i] += __shfl_xor_sync(0xffffffffu, rs[i], 4);
            rs[i] += __shfl_xor_sync(0xffffffffu, rs[i], 8);
        }
        if (tx == 0) {
#pragma unroll
            for (int i = 0; i < 4; i++) l_s[ty * 4 + i] += rs[i];
        }
        __syncthreads();

        // O += P V (no rescale needed)
#pragma unroll 2
        for (int j = 0; j < 64; j++) {
            float4 vv = *(const float4*)&Vs[j][tx * 4];
            float vf[4] = {vv.x, vv.y, vv.z, vv.w};
#pragma unroll
            for (int i = 0; i < 4; i++) {
                float p = sc[ty * 4 + i][j];
#pragma unroll
                for (int jj = 0; jj < 4; jj++) acc[i][jj] += p * vf[jj];
            }
        }
    }

    // ---- 3 extra (diagonal) keys: cache_k[1], cache_k[2], current k ----
    __syncthreads();
    {
        int rr = lr, lane = tid & 3;
        if (lane < 3) {
            int s = q0 + rr;
            const float* kvec;
            if (lane < 2)
                kvec = cache_k + (((size_t)(1 + lane) * Bb * NHH + bh) * SS + s) * 64;
            else
                kvec = kcur + (((size_t)b * NKVV + (h >> 2)) * SS + s) * 64;
            float dot = 0.f;
#pragma unroll 8
            for (int d = 0; d < 64; d++) dot += Qs[d][rr] * kvec[d];
            sc[rr][lane] = __expf(dot * scale);
        }
    }
    __syncthreads();
    if (tx == 0) {
#pragma unroll
        for (int i = 0; i < 4; i++) {
            int rr2 = ty * 4 + i;
            l_s[rr2] += sc[rr2][0] + sc[rr2][1] + sc[rr2][2];
        }
    }
    __syncthreads();
#pragma unroll
    for (int i = 0; i < 4; i++) {
        int s = q0 + ty * 4 + i;
#pragma unroll
        for (int n = 0; n < 3; n++) {
            const float* vvec = (n < 2)
                ? cache_v + (((size_t)(1 + n) * Bb * NHH + bh) * SS + s) * 64
                : vcur + (((size_t)b * NKVV + (h >> 2)) * SS + s) * 64;
            float p = sc[ty * 4 + i][n];
            float4 vv = *(const float4*)(vvec + tx * 4);
            acc[i][0] += p * vv.x; acc[i][1] += p * vv.y;
            acc[i][2] += p * vv.z; acc[i][3] += p * vv.w;
        }
    }
#pragma unroll
    for (int i = 0; i < 4; i++) {
        int s = q0 + ty * 4 + i;
        float inv = 1.0f / l_s[ty * 4 + i];
        size_t oidx = ((size_t)(b * SS + s)) * HH + h * 64 + tx * 4;
#pragma unroll
        for (int j = 0; j < 4; j++) {
            __nv_bfloat16 hv, lv;
            split2(acc[i][j] * inv, hv, lv);
            ohi[oidx + j] = hv;
            olo[oidx + j] = lv;
        }
    }
}

// SiLU(gate)*up -> split bf16 pair
__global__ __launch_bounds__(256) void silu_split_kernel(
    const float* __restrict__ gu, __nv_bfloat16* __restrict__ hi,
    __nv_bfloat16* __restrict__ lo)
{
    int i = blockIdx.x * 256 + threadIdx.x;
    int row = i >> 13, col = i & 8191;
    float g = gu[(size_t)row * 16384 + col];
    float u = gu[(size_t)row * 16384 + 8192 + col];
    float a = g / (1.0f + expf(-g)) * u;
    __nv_bfloat16 hv, lv;
    split2(a, hv, lv);
    hi[i] = hv; lo[i] = lv;
}

// ================= launcher =================
extern "C" void kernel_launch(void* const* d_in, const int* in_sizes, int n_in,
                              void* d_out, int out_size)
{
    const float* input_emb     = (const float*)d_in[0];
    const float* hidden_states = (const float*)d_in[1];
    const float* cache_k       = (const float*)d_in[2];
    const float* cache_v       = (const float*)d_in[3];
    const int*   position_ids  = (const int*)d_in[5];
    const float* wq            = (const float*)d_in[6];
    const float* wk            = (const float*)d_in[7];
    const float* wv            = (const float*)d_in[8];
    const float* wo            = (const float*)d_in[9];
    const float* w_gate        = (const float*)d_in[10];
    const float* w_up          = (const float*)d_in[11];
    const float* w_down        = (const float*)d_in[12];
    const float* hidden_norm_w = (const float*)d_in[13];
    const float* input_ln_w    = (const float*)d_in[14];
    const float* post_ln_w     = (const float*)d_in[15];
    float* out = (float*)d_out;

    __nv_bfloat16 *xhi, *xlo, *wqkvh, *wqkvl, *woh, *wol, *wguh, *wgul, *wdnh, *wdnl;
    __nv_bfloat16 *ahi, *alo, *hnhi, *hnlo, *acth, *actl;
    float *qkv, *q, *k, *v, *h2, *gu;
    cudaGetSymbolAddress((void**)&xhi, g_xhi);     cudaGetSymbolAddress((void**)&xlo, g_xlo);
    cudaGetSymbolAddress((void**)&wqkvh, g_wqkv_hi); cudaGetSymbolAddress((void**)&wqkvl, g_wqkv_lo);
    cudaGetSymbolAddress((void**)&woh, g_wo_hi);   cudaGetSymbolAddress((void**)&wol, g_wo_lo);
    cudaGetSymbolAddress((void**)&wguh, g_wgu_hi); cudaGetSymbolAddress((void**)&wgul, g_wgu_lo);
    cudaGetSymbolAddress((void**)&wdnh, g_wdn_hi); cudaGetSymbolAddress((void**)&wdnl, g_wdn_lo);
    cudaGetSymbolAddress((void**)&ahi, g_ahi);     cudaGetSymbolAddress((void**)&alo, g_alo);
    cudaGetSymbolAddress((void**)&hnhi, g_hnhi);   cudaGetSymbolAddress((void**)&hnlo, g_hnlo);
    cudaGetSymbolAddress((void**)&acth, g_acthi);  cudaGetSymbolAddress((void**)&actl, g_actlo);
    cudaGetSymbolAddress((void**)&qkv, g_qkv);
    cudaGetSymbolAddress((void**)&q, g_q);
    cudaGetSymbolAddress((void**)&k, g_k);
    cudaGetSymbolAddress((void**)&v, g_v);
    cudaGetSymbolAddress((void**)&h2, g_h2);
    cudaGetSymbolAddress((void**)&gu, g_gu);

    cudaFuncSetAttribute(gemm_mma, cudaFuncAttributeMaxDynamicSharedMemorySize, GEMM_DSMEM);
    const int attn_smem = (4 * 64 * 68 + 64) * (int)sizeof(float);
    cudaFuncSetAttribute(attn_kernel, cudaFuncAttributeMaxDynamicSharedMemorySize, attn_smem);

    // Launch order arranged so ncu (-s 5 -c 1) captures attn_kernel (index 5).
    // 0: packed QKV weight convert
    convert_qkv_kernel<<<3072 * 4096 / 1024, 256>>>(wq, wk, wv, wqkvh, wqkvl);
    // 1: norms + concat (split bf16)
    rmsnorm_concat_kernel<<<TOK, 256>>>(input_emb, hidden_states, input_ln_w, hidden_norm_w, xhi, xlo);
    // 2: QKV GEMM (packed, N=3072)
    gemm_mma<<<dim3(3072 / 128, TOK / 128), 256, GEMM_DSMEM>>>(xhi, xlo, wqkvh, wqkvl, nullptr, qkv, 3072, 4096, 0);
    // 3: RoPE + reshape
    rope_kernel<<<TOK, 256>>>(qkv, position_ids, q, k, v);
    // 4: wo convert (needed before launch 6)
    convert_split_kernel<<<2048 * 2048 / 1024, 256>>>(wo, woh, wol, 2048 * 2048);
    // 5: attention -> split bf16   (ncu capture target)
    attn_kernel<<<dim3(SS / 64, NHH, Bb), 256, attn_smem>>>(q, cache_k, cache_v, k, v, ahi, alo);
    // 6: out projection + residual
    gemm_mma<<<dim3(2048 / 128, TOK / 128), 256, GEMM_DSMEM>>>(ahi, alo, woh, wol, hidden_states, h2, 2048, 2048, 1);
    // 7: post-attn norm -> split bf16
    rmsnorm_split_kernel<<<TOK, 256>>>(h2, post_ln_w, hnhi, hnlo);
    // 8,9: gate|up weight converts
    convert_split_kernel<<<8192 * 2048 / 1024, 256>>>(w_gate, wguh, wgul, 8192 * 2048);
    convert_split_kernel<<<8192 * 2048 / 1024, 256>>>(w_up, wguh + 8192 * 2048, wgul + 8192 * 2048, 8192 * 2048);
    // 10: gate|up GEMM (packed, N=16384)
    gemm_mma<<<dim3(16384 / 128, TOK / 128), 256, GEMM_DSMEM>>>(hnhi, hnlo, wguh, wgul, nullptr, gu, 16384, 2048, 0);
    // 11: SiLU * up -> split bf16
    silu_split_kernel<<<TOK * IIF / 256, 256>>>(gu, acth, actl);
    // 12: w_down convert
    convert_split_kernel<<<2048 * 8192 / 1024, 256>>>(w_down, wdnh, wdnl, 2048 * 8192);
    // 13: down projection + residual -> final output
    gemm_mma<<<dim3(2048 / 128, TOK / 128), 256, GEMM_DSMEM>>>(acth, actl, wdnh, wdnl, h2, out, 2048, 8192, 1);

    (void)in_sizes; (void)n_in; (void)out_size;
}

// round 16
// speedup vs baseline: 1.1907x; 1.0616x over previous
#include <cuda_runtime.h>
#include <cuda_bf16.h>
#include <cstdint>
#include <math.h>

// Shapes (fixed by the problem)
#define Bb   2
#define SS   1024
#define HH   2048
#define NHH  32
#define NKVV 8
#define DD   64
#define IIF  8192
#define TOK  (Bb*SS)          // 2048 tokens
#define LCK  3

// ================= PTX helpers (arch-neutral: sm_80+ instructions only) ======
__device__ __forceinline__ uint32_t smem_to_u32(const void* p) {
    uint32_t a;
    asm("{ .reg .u64 t; cvta.to.shared.u64 t, %1; cvt.u32.u64 %0, t; }" : "=r"(a) : "l"(p));
    return a;
}

__device__ __forceinline__ void cp16(uint32_t s, const void* g) {
    asm volatile("cp.async.cg.shared.global [%0], [%1], 16;" :: "r"(s), "l"(g) : "memory");
}
#define CP_COMMIT() asm volatile("cp.async.commit_group;" ::: "memory")
#define CP_WAIT(n)  asm volatile("cp.async.wait_group %0;" :: "n"(n) : "memory")

__device__ __forceinline__ void ldsm4(uint32_t* r, uint32_t addr) {
    asm volatile("ldmatrix.sync.aligned.m8n8.x4.shared.b16 {%0,%1,%2,%3}, [%4];"
                 : "=r"(r[0]), "=r"(r[1]), "=r"(r[2]), "=r"(r[3]) : "r"(addr));
}

#define MMA_BF16(c, a, b0, b1)                                            \
    asm volatile("mma.sync.aligned.m16n8k16.row.col.f32.bf16.bf16.f32 "   \
        "{%0,%1,%2,%3}, {%4,%5,%6,%7}, {%8,%9}, {%0,%1,%2,%3};"           \
        : "+f"((c)[0]), "+f"((c)[1]), "+f"((c)[2]), "+f"((c)[3])          \
        : "r"((a)[0]), "r"((a)[1]), "r"((a)[2]), "r"((a)[3]),             \
          "r"(b0), "r"(b1))

// ================= scratch (device globals) =================
__device__ __nv_bfloat16 g_xhi[TOK * 4096],   g_xlo[TOK * 4096];
__device__ __nv_bfloat16 g_wqkv_hi[3072 * 4096],  g_wqkv_lo[3072 * 4096];
__device__ __nv_bfloat16 g_wo_hi[2048 * 2048],    g_wo_lo[2048 * 2048];
__device__ __nv_bfloat16 g_wgu_hi[16384 * 2048],  g_wgu_lo[16384 * 2048];
__device__ __nv_bfloat16 g_wdn_hi[2048 * 8192],   g_wdn_lo[2048 * 8192];
__device__ __nv_bfloat16 g_ahi[TOK * 2048],   g_alo[TOK * 2048];   // attention out
__device__ __nv_bfloat16 g_hnhi[TOK * 2048],  g_hnlo[TOK * 2048];
__device__ __nv_bfloat16 g_acthi[TOK * 8192], g_actlo[TOK * 8192];
__device__ float g_qkv[TOK * 3072];
__device__ float g_q[Bb * NHH * SS * DD];
__device__ float g_k[Bb * NKVV * SS * DD];
__device__ float g_v[Bb * NKVV * SS * DD];
__device__ float g_h2[TOK * 2048];
__device__ float g_gu[TOK * 16384];
// attention bf16 operands
__device__ __nv_bfloat16 g_qh[Bb * NHH * SS * DD], g_ql[Bb * NHH * SS * DD];
__device__ __nv_bfloat16 g_k0h[Bb * NHH * SS * DD], g_k0l[Bb * NHH * SS * DD];
__device__ __nv_bfloat16 g_vth[Bb * NHH * DD * SS], g_vtl[Bb * NHH * DD * SS]; // [bh][d][s]

__device__ __forceinline__ void split2(float x, __nv_bfloat16& h, __nv_bfloat16& l) {
    h = __float2bfloat16(x);
    l = __float2bfloat16(x - __bfloat162float(h));
}
__device__ __forceinline__ void packsplit(float x, float y, uint32_t& hi, uint32_t& lo) {
    __nv_bfloat16 hx = __float2bfloat16(x), hy = __float2bfloat16(y);
    __nv_bfloat16 lx = __float2bfloat16(x - __bfloat162float(hx));
    __nv_bfloat16 ly = __float2bfloat16(y - __bfloat162float(hy));
    __nv_bfloat162 ph(hx, hy), pl(lx, ly);
    hi = *(uint32_t*)&ph; lo = *(uint32_t*)&pl;
}

// ================= tensor-core GEMM (mma.sync bf16, 3-pass split) ============
// (unchanged R8/R14 winner configuration)
#define ROWB       80
#define MAT_BYTES  (128 * ROWB)
#define STG_BYTES  (4 * MAT_BYTES)       // 40960 (Ah | Al | Bh | Bl)
#define GEMM_DSMEM (2 * STG_BYTES)       // 81920

__device__ __forceinline__ void stage_mat(uint32_t smat, const __nv_bfloat16* __restrict__ src,
                                          int row0, int K, int k0, int tid) {
#pragma unroll
    for (int h = 0; h < 2; h++) {
        int idx = tid + h * 256;
        int row = idx >> 2, c = idx & 3;
        cp16(smat + row * ROWB + c * 16,
             src + (size_t)(row0 + row) * K + k0 + c * 8);
    }
}

__global__ __launch_bounds__(256, 2) void gemm_mma(
    const __nv_bfloat16* __restrict__ Ahi, const __nv_bfloat16* __restrict__ Alo,
    const __nv_bfloat16* __restrict__ Bhi, const __nv_bfloat16* __restrict__ Blo,
    const float* __restrict__ resid, float* __restrict__ C,
    int ldc, int K, int addResid)
{
    extern __shared__ char dsm[];
    uint32_t sbase = smem_to_u32(dsm);
    int tid = threadIdx.x, wid = tid >> 5, lane = tid & 31;
    int m0 = blockIdx.y * 128, n0 = blockIdx.x * 128;
    int wm = (wid & 1) * 64;
    int wn = (wid >> 1) * 32;
    int tile = lane >> 3, r = lane & 7;

    float acc[4][4][4];
#pragma unroll
    for (int f = 0; f < 4; f++)
#pragma unroll
        for (int n = 0; n < 4; n++)
#pragma unroll
            for (int e = 0; e < 4; e++) acc[f][n][e] = 0.f;

    int nK = K >> 5;
    {
        stage_mat(sbase,                 Ahi, m0, K, 0, tid);
        stage_mat(sbase + MAT_BYTES,     Alo, m0, K, 0, tid);
        stage_mat(sbase + 2 * MAT_BYTES, Bhi, n0, K, 0, tid);
        stage_mat(sbase + 3 * MAT_BYTES, Blo, n0, K, 0, tid);
        CP_COMMIT();
    }

    uint32_t aoff = (uint32_t)((((tile & 1) << 3) + r) * ROWB + ((tile >> 1) << 4));
    uint32_t boff = (uint32_t)((((tile >> 1) << 3) + r) * ROWB + ((tile & 1) << 4));

    for (int ks = 0; ks < nK; ks++) {
        int nxt = ks + 1;
        if (nxt < nK) {
            uint32_t sp = sbase + (nxt & 1) * STG_BYTES;
            int k0 = nxt << 5;
            stage_mat(sp,                 Ahi, m0, K, k0, tid);
            stage_mat(sp + MAT_BYTES,     Alo, m0, K, k0, tid);
            stage_mat(sp + 2 * MAT_BYTES, Bhi, n0, K, k0, tid);
            stage_mat(sp + 3 * MAT_BYTES, Blo, n0, K, k0, tid);
            CP_COMMIT();
            CP_WAIT(1);
        } else {
            CP_WAIT(0);
        }
        __syncthreads();

        uint32_t so = sbase + (ks & 1) * STG_BYTES;
        uint32_t aHb = so + (uint32_t)(wm * ROWB);
        uint32_t aLb = aHb + MAT_BYTES;
        uint32_t bHb = so + 2 * MAT_BYTES + (uint32_t)(wn * ROWB);
        uint32_t bLb = bHb + MAT_BYTES;

#pragma unroll
        for (int kk = 0; kk < 2; kk++) {
            uint32_t Ah[4][4], Al[4][4], Bh[2][4], Bl[2][4];
            uint32_t kadd = (uint32_t)(kk << 5);
#pragma unroll
            for (int f = 0; f < 4; f++) {
                uint32_t off = aoff + (uint32_t)(f * 16 * ROWB) + kadd;
                ldsm4(Ah[f], aHb + off);
                ldsm4(Al[f], aLb + off);
            }
#pragma unroll
            for (int g = 0; g < 2; g++) {
                uint32_t off = boff + (uint32_t)(g * 16 * ROWB) + kadd;
                ldsm4(Bh[g], bHb + off);
                ldsm4(Bl[g], bLb + off);
            }
#pragma unroll
            for (int f = 0; f < 4; f++) {
#pragma unroll
                for (int n = 0; n < 4; n++) {
                    const uint32_t* bh = &Bh[n >> 1][(n & 1) * 2];
                    const uint32_t* bl = &Bl[n >> 1][(n & 1) * 2];
                    MMA_BF16(acc[f][n], Ah[f], bh[0], bh[1]);
                    MMA_BF16(acc[f][n], Ah[f], bl[0], bl[1]);
                    MMA_BF16(acc[f][n], Al[f], bh[0], bh[1]);
                }
            }
        }
        __syncthreads();
    }

    int rr = lane >> 2, cc = (lane & 3) * 2;
#pragma unroll
    for (int f = 0; f < 4; f++) {
#pragma unroll
        for (int n = 0; n < 4; n++) {
            int m = m0 + wm + f * 16 + rr;
            int c = n0 + wn + n * 8 + cc;
            size_t i0 = (size_t)m * ldc + c;
            size_t i1 = (size_t)(m + 8) * ldc + c;
            float2 v0 = make_float2(acc[f][n][0], acc[f][n][1]);
            float2 v1 = make_float2(acc[f][n][2], acc[f][n][3]);
            if (addResid) {
                float2 r0 = *(const float2*)(resid + i0);
                float2 r1 = *(const float2*)(resid + i1);
                v0.x += r0.x; v0.y += r0.y;
                v1.x += r1.x; v1.y += r1.y;
            }
            *(float2*)(C + i0) = v0;
            *(float2*)(C + i1) = v1;
        }
    }
}

// ================= small kernels =================
__device__ __forceinline__ float blockReduceSum(float v) {
    __shared__ float red[8];
    int lane = threadIdx.x & 31, w = threadIdx.x >> 5;
#pragma unroll
    for (int o = 16; o; o >>= 1) v += __shfl_xor_sync(0xffffffffu, v, o);
    if (lane == 0) red[w] = v;
    __syncthreads();
    if (w == 0) {
        float t = (lane < 8) ? red[lane] : 0.0f;
#pragma unroll
        for (int o = 4; o; o >>= 1) t += __shfl_xor_sync(0xffffffffu, t, o);
        if (lane == 0) red[0] = t;
    }
    __syncthreads();
    float r = red[0];
    __syncthreads();
    return r;
}

__global__ __launch_bounds__(256) void rmsnorm_concat_kernel(
    const float* __restrict__ emb, const float* __restrict__ hid,
    const float* __restrict__ w_e, const float* __restrict__ w_h,
    __nv_bfloat16* __restrict__ xhi, __nv_bfloat16* __restrict__ xlo)
{
    int t = blockIdx.x;
    const float* e  = emb + (size_t)t * HH;
    const float* hh = hid + (size_t)t * HH;
    float se = 0.f, sh = 0.f;
    for (int i = threadIdx.x; i < HH; i += 256) {
        float a = e[i];  se += a * a;
        float c = hh[i]; sh += c * c;
    }
    se = blockReduceSum(se);
    sh = blockReduceSum(sh);
    float re = rsqrtf(se / (float)HH + 1e-6f);
    float rh = rsqrtf(sh / (float)HH + 1e-6f);
    size_t ro = (size_t)t * 4096;
    for (int i = threadIdx.x; i < HH; i += 256) {
        __nv_bfloat16 hv, lv;
        split2(w_e[i] * e[i] * re, hv, lv);
        xhi[ro + i] = hv; xlo[ro + i] = lv;
        split2(w_h[i] * hh[i] * rh, hv, lv);
        xhi[ro + HH + i] = hv; xlo[ro + HH + i] = lv;
    }
}

__global__ __launch_bounds__(256) void rmsnorm_split_kernel(
    const float* __restrict__ in, const float* __restrict__ w,
    __nv_bfloat16* __restrict__ ohi, __nv_bfloat16* __restrict__ olo)
{
    int t = blockIdx.x;
    const float* r = in + (size_t)t * HH;
    float s = 0.f;
    for (int i = threadIdx.x; i < HH; i += 256) { float a = r[i]; s += a * a; }
    s = blockReduceSum(s);
    float inv = rsqrtf(s / (float)HH + 1e-6f);
    size_t ro = (size_t)t * HH;
    for (int i = threadIdx.x; i < HH; i += 256) {
        __nv_bfloat16 hv, lv;
        split2(w[i] * r[i] * inv, hv, lv);
        ohi[ro + i] = hv; olo[ro + i] = lv;
    }
}

__global__ __launch_bounds__(256) void convert_split_kernel(
    const float* __restrict__ src, __nv_bfloat16* __restrict__ hi,
    __nv_bfloat16* __restrict__ lo, int n)
{
    int i = (blockIdx.x * 256 + threadIdx.x) * 4;
    if (i < n) {
        float4 v = *(const float4*)(src + i);
        __nv_bfloat16 h0, l0, h1, l1, h2, l2, h3, l3;
        split2(v.x, h0, l0); split2(v.y, h1, l1);
        split2(v.z, h2, l2); split2(v.w, h3, l3);
        __nv_bfloat162* ph = (__nv_bfloat162*)(hi + i);
        __nv_bfloat162* pl = (__nv_bfloat162*)(lo + i);
        ph[0] = __nv_bfloat162(h0, h1); ph[1] = __nv_bfloat162(h2, h3);
        pl[0] = __nv_bfloat162(l0, l1); pl[1] = __nv_bfloat162(l2, l3);
    }
}

// combined wq|wk|wv convert into the packed QKV weight buffer
__global__ __launch_bounds__(256) void convert_qkv_kernel(
    const float* __restrict__ wq, const float* __restrict__ wk,
    const float* __restrict__ wv, __nv_bfloat16* __restrict__ hi,
    __nv_bfloat16* __restrict__ lo)
{
    int i = (blockIdx.x * 256 + threadIdx.x) * 4;   // over 3072*4096
    int row = i >> 12;
    const float* src;
    if (row < 2048)       src = wq + i;
    else if (row < 2560)  src = wk + (i - 2048 * 4096);
    else                  src = wv + (i - 2560 * 4096);
    float4 v = *(const float4*)src;
    __nv_bfloat16 h0, l0, h1, l1, h2, l2, h3, l3;
    split2(v.x, h0, l0); split2(v.y, h1, l1);
    split2(v.z, h2, l2); split2(v.w, h3, l3);
    __nv_bfloat162* ph = (__nv_bfloat162*)(hi + i);
    __nv_bfloat162* pl = (__nv_bfloat162*)(lo + i);
    ph[0] = __nv_bfloat162(h0, h1); ph[1] = __nv_bfloat162(h2, h3);
    pl[0] = __nv_bfloat162(l0, l1); pl[1] = __nv_bfloat162(l2, l3);
}

// transpose cache_v[0] to [bh][d][s] bf16 hi/lo (validated in R6)
__global__ __launch_bounds__(256) void transpose_v0_kernel(
    const float* __restrict__ v0, __nv_bfloat16* __restrict__ vth,
    __nv_bfloat16* __restrict__ vtl)
{
    __shared__ float ts[64][65];
    int s0 = blockIdx.x * 64;
    int bh = blockIdx.y;
    int tid = threadIdx.x;
    int row = tid >> 2, cq = (tid & 3) * 16;
    const float* src = v0 + ((size_t)bh * SS + s0 + row) * 64 + cq;
#pragma unroll
    for (int c4 = 0; c4 < 4; c4++) {
        float4 v = *(const float4*)(src + c4 * 4);
        ts[row][cq + c4 * 4 + 0] = v.x;
        ts[row][cq + c4 * 4 + 1] = v.y;
        ts[row][cq + c4 * 4 + 2] = v.z;
        ts[row][cq + c4 * 4 + 3] = v.w;
    }
    __syncthreads();
    int drow = tid >> 2;
    size_t ob = (size_t)bh * 64 * SS + (size_t)drow * SS + s0 + cq;
#pragma unroll
    for (int c2 = 0; c2 < 8; c2++) {
        float x = ts[cq + c2 * 2][drow];
        float y = ts[cq + c2 * 2 + 1][drow];
        uint32_t hi, lo;
        packsplit(x, y, hi, lo);
        *(uint32_t*)(vth + ob + c2 * 2) = hi;
        *(uint32_t*)(vtl + ob + c2 * 2) = lo;
    }
}

// RoPE + layout transform; q also emitted as bf16 hi/lo (validated in R6)
__global__ __launch_bounds__(256) void rope_kernel(
    const float* __restrict__ qkv, const int* __restrict__ pos_ids,
    float* __restrict__ q, float* __restrict__ k, float* __restrict__ v,
    __nv_bfloat16* __restrict__ qh, __nv_bfloat16* __restrict__ ql)
{
    int t = blockIdx.x;
    int b = t >> 10, s = t & 1023;
    float pos = (float)(pos_ids[t] + LCK);
    const float* row = qkv + (size_t)t * 3072;
    const float lg = logf(10000.0f) / 32.0f;

    for (int p = threadIdx.x; p < 1024 + 256; p += 256) {
        const float* src; float* dst; int hh, d; size_t qb = 0; bool isq = (p < 1024);
        if (isq) {
            hh = p >> 5; d = p & 31;
            src = row + hh * 64;
            qb = (((size_t)b * NHH + hh) * SS + s) * 64;
            dst = q + qb;
        } else {
            int pp = p - 1024;
            hh = pp >> 5; d = pp & 31;
            src = row + 2048 + hh * 64;
            dst = k + (((size_t)b * NKVV + hh) * SS + s) * 64;
        }
        float invf = expf(-(float)d * lg);
        float ang = pos * invf;
        float c = cosf(ang), sn = sinf(ang);
        float x0 = src[d], x1 = src[d + 32];
        float r0 = x0 * c - x1 * sn;
        float r1 = x1 * c + x0 * sn;
        dst[d]      = r0;
        dst[d + 32] = r1;
        if (isq) {
            __nv_bfloat16 hv, lv;
            split2(r0, hv, lv); qh[qb + d] = hv;      ql[qb + d] = lv;
            split2(r1, hv, lv); qh[qb + d + 32] = hv; ql[qb + d + 32] = lv;
        }
    }
    for (int p = threadIdx.x; p < 512; p += 256) {
        int hh = p >> 6, d = p & 63;
        v[(((size_t)b * NKVV + hh) * SS + s) * 64 + d] = row[2560 + p];
    }
}

// ================= tensor-core flash attention (v2) =================
// CTA: 64 q-rows of one (b,h); 128 threads = 4 warps, each warp 16 rows.
// KV processed in 64-row blocks, double-buffered cp.async. 93.2 KB smem
// -> 2 CTAs/SM. Q frags register-resident. No-max softmax. 3-pass split.
#define ROWQ 144
#define AQH  0
#define AQL  9216
#define ASTG 18432
#define ASTG_SZ 36864   // Kh 9216 | Kl 9216 | Vh 9216 | Vl 9216
#define ADOTS (ASTG + 2 * ASTG_SZ)    // 92160
#define ATTN2_DSMEM (ADOTS + 1024)    // 93184

__global__ __launch_bounds__(128, 2) void attn_tc_kernel(
    const __nv_bfloat16* __restrict__ qh, const __nv_bfloat16* __restrict__ ql,
    const __nv_bfloat16* __restrict__ k0h, const __nv_bfloat16* __restrict__ k0l,
    const __nv_bfloat16* __restrict__ vth, const __nv_bfloat16* __restrict__ vtl,
    const float* __restrict__ qf, const float* __restrict__ cache_k,
    const float* __restrict__ cache_v, const float* __restrict__ kcur,
    const float* __restrict__ vcur,
    __nv_bfloat16* __restrict__ ohi, __nv_bfloat16* __restrict__ olo)
{
    extern __shared__ char dsm[];
    uint32_t sb = smem_to_u32(dsm);
    float* sdots = (float*)(dsm + ADOTS);
    int tid = threadIdx.x, wid = tid >> 5, lane = tid & 31;
    int qt = gridDim.x - 1 - blockIdx.x;     // LPT
    int h = blockIdx.y, b = blockIdx.z;
    int q0 = qt * 64;
    int bh = b * NHH + h;
    int wm = wid * 16;
    int tile = lane >> 3, r = lane & 7;
    const float scale = 0.125f;

    const __nv_bfloat16* kbh = k0h + (size_t)bh * SS * 64;
    const __nv_bfloat16* kbl = k0l + (size_t)bh * SS * 64;
    const __nv_bfloat16* vbh = vth + (size_t)bh * 64 * SS;
    const __nv_bfloat16* vbl = vtl + (size_t)bh * 64 * SS;

    // ---- stage Q (hi/lo) + KV block 0, one cp.async group ----
    {
        const __nv_bfloat16* qsh = qh + ((size_t)bh * SS + q0) * 64;
        const __nv_bfloat16* qsl = ql + ((size_t)bh * SS + q0) * 64;
        for (int i = tid; i < 512; i += 128) {
            int row = i >> 3, c = i & 7;
            cp16(sb + AQH + row * ROWQ + c * 16, qsh + row * 64 + c * 8);
            cp16(sb + AQL + row * ROWQ + c * 16, qsl + row * 64 + c * 8);
        }
    }
#define LOAD_KV(kb, st)                                                        \
    do {                                                                       \
        uint32_t sg2 = sb + ASTG + (st) * ASTG_SZ;                             \
        for (int i = tid; i < 2048; i += 128) {                                \
            int m = i >> 9, j = i & 511;                                       \
            int row = j >> 3, c = j & 7;                                       \
            uint32_t dst = sg2 + m * 9216 + row * ROWQ + c * 16;               \
            const __nv_bfloat16* src;                                          \
            if (m == 0)      src = kbh + ((size_t)(kb) * 64 + row) * 64 + c * 8; \
            else if (m == 1) src = kbl + ((size_t)(kb) * 64 + row) * 64 + c * 8; \
            else if (m == 2) src = vbh + (size_t)row * SS + (kb) * 64 + c * 8;   \
            else             src = vbl + (size_t)row * SS + (kb) * 64 + c * 8;   \
        cp16(dst, src);                                                        \
        }                                                                      \
        CP_COMMIT();                                                           \
    } while (0)

    LOAD_KV(0, 0);
    CP_WAIT(0);
    __syncthreads();

    // ---- Q frags to registers (A-frag pattern, as in gemm_mma) ----
    uint32_t qaoff = (uint32_t)((wm + ((tile & 1) << 3) + r) * ROWQ + ((tile >> 1) << 4));
    uint32_t Qh4[4][4], Ql4[4][4];
#pragma unroll
    for (int kk = 0; kk < 4; kk++) {
        ldsm4(Qh4[kk], sb + AQH + qaoff + kk * 32);
        ldsm4(Ql4[kk], sb + AQL + qaoff + kk * 32);
    }

    uint32_t boffB = (uint32_t)((((tile >> 1) << 3) + r) * ROWQ + ((tile & 1) << 4));
    int r0loc = wm + (lane >> 2);
    int cbase = 2 * (lane & 3);

    float oacc[8][4];
#pragma unroll
    for (int j = 0; j < 8; j++)
#pragma unroll
        for (int e = 0; e < 4; e++) oacc[j][e] = 0.f;
    float l0 = 0.f, l1 = 0.f;

    for (int kb = 0; kb <= qt; kb++) {
        if (kb < qt) { LOAD_KV(kb + 1, (kb + 1) & 1); CP_WAIT(1); }
        else         { CP_WAIT(0); }
        __syncthreads();

        uint32_t sg = sb + ASTG + (kb & 1) * ASTG_SZ;
        uint32_t sKH = sg, sKL = sg + 9216, sVH = sg + 18432, sVL = sg + 27648;

        // ---- S = Q K^T (3-pass split) ----
        float sf[8][4];
#pragma unroll
        for (int j = 0; j < 8; j++)
#pragma unroll
            for (int e = 0; e < 4; e++) sf[j][e] = 0.f;
#pragma unroll
        for (int kk = 0; kk < 4; kk++) {
#pragma unroll
            for (int g = 0; g < 4; g++) {
                uint32_t Bh4[4], Bl4[4];
                uint32_t off = boffB + (uint32_t)(g * 16 * ROWQ) + kk * 32;
                ldsm4(Bh4, sKH + off);
                ldsm4(Bl4, sKL + off);
                MMA_BF16(sf[2 * g],     Qh4[kk], Bh4[0], Bh4[1]);
                MMA_BF16(sf[2 * g],     Qh4[kk], Bl4[0], Bl4[1]);
                MMA_BF16(sf[2 * g],     Ql4[kk], Bh4[0], Bh4[1]);
                MMA_BF16(sf[2 * g + 1], Qh4[kk], Bh4[2], Bh4[3]);
                MMA_BF16(sf[2 * g + 1], Qh4[kk], Bl4[2], Bl4[3]);
                MMA_BF16(sf[2 * g + 1], Ql4[kk], Bh4[2], Bh4[3]);
            }
        }
        // ---- scale + mask + exp + row sums ----
        bool diag = (kb == qt);
        float ls0 = 0.f, ls1 = 0.f;
#pragma unroll
        for (int j = 0; j < 8; j++) {
#pragma unroll
            for (int e = 0; e < 4; e++) {
                float s = sf[j][e] * scale;
                if (diag) {
                    int col = 8 * j + cbase + (e & 1);
                    int rowl = r0loc + ((e < 2) ? 0 : 8);
                    if (col > rowl) s = -1e30f;
                }
                s = __expf(s);
                sf[j][e] = s;
                if (e < 2) ls0 += s; else ls1 += s;
            }
        }
        ls0 += __shfl_xor_sync(0xffffffffu, ls0, 1);
        ls0 += __shfl_xor_sync(0xffffffffu, ls0, 2);
        ls1 += __shfl_xor_sync(0xffffffffu, ls1, 1);
        ls1 += __shfl_xor_sync(0xffffffffu, ls1, 2);
        l0 += ls0; l1 += ls1;

        // ---- O += P V (3-pass split); P frags direct from sf ----
#pragma unroll
        for (int kk2 = 0; kk2 < 4; kk2++) {
            uint32_t Ph[4], Pl[4];
            int j0 = 2 * kk2, j1 = 2 * kk2 + 1;
            packsplit(sf[j0][0], sf[j0][1], Ph[0], Pl[0]);
            packsplit(sf[j0][2], sf[j0][3], Ph[1], Pl[1]);
            packsplit(sf[j1][0], sf[j1][1], Ph[2], Pl[2]);
            packsplit(sf[j1][2], sf[j1][3], Ph[3], Pl[3]);
#pragma unroll
            for (int g = 0; g < 4; g++) {
                uint32_t Vh4[4], Vl4[4];
                uint32_t off = boffB + (uint32_t)(g * 16 * ROWQ) + kk2 * 32;
                ldsm4(Vh4, sVH + off);
                ldsm4(Vl4, sVL + off);
                MMA_BF16(oacc[2 * g],     Ph, Vh4[0], Vh4[1]);
                MMA_BF16(oacc[2 * g],     Ph, Vl4[0], Vl4[1]);
                MMA_BF16(oacc[2 * g],     Pl, Vh4[0], Vh4[1]);
                MMA_BF16(oacc[2 * g + 1], Ph, Vh4[2], Vh4[3]);
                MMA_BF16(oacc[2 * g + 1], Ph, Vl4[2], Vl4[3]);
                MMA_BF16(oacc[2 * g + 1], Pl, Vh4[2], Vh4[3]);
            }
        }
        __syncthreads();
    }

    // ---- 3 extra (diagonal) keys in exact fp32: cache_k[1], cache_k[2], current k
    for (int t = tid; t < 192; t += 128) {
        int row = t & 63, n = t >> 6;
        int s = q0 + row;
        const float* qrow = qf + ((size_t)bh * SS + s) * 64;
        const float* kvec;
        if (n < 2)
            kvec = cache_k + ((size_t)(1 + n) * Bb * NHH + bh) * SS * 64 + (size_t)s * 64;
        else
            kvec = kcur + (((size_t)b * NKVV + (h >> 2)) * SS + s) * 64;
        float dot = 0.f;
#pragma unroll 8
        for (int d = 0; d < 64; d++) dot += qrow[d] * kvec[d];
        sdots[row * 4 + n] = __expf(dot * scale);
    }
    __syncthreads();
    {
        int sA = q0 + r0loc, sB = sA + 8;
        float pA[3], pB[3];
#pragma unroll
        for (int n = 0; n < 3; n++) {
            pA[n] = sdots[r0loc * 4 + n];
            pB[n] = sdots[(r0loc + 8) * 4 + n];
        }
        l0 += pA[0] + pA[1] + pA[2];
        l1 += pB[0] + pB[1] + pB[2];
#pragma unroll
        for (int n = 0; n < 3; n++) {
            const float* vA;
            const float* vB;
            if (n < 2) {
                const float* vb2 = cache_v + ((size_t)(1 + n) * Bb * NHH + bh) * SS * 64;
                vA = vb2 + (size_t)sA * 64;
                vB = vb2 + (size_t)sB * 64;
            } else {
                const float* vb2 = vcur + ((size_t)b * NKVV + (h >> 2)) * SS * 64;
                vA = vb2 + (size_t)sA * 64;
                vB = vb2 + (size_t)sB * 64;
            }
#pragma unroll
            for (int j = 0; j < 8; j++) {
                int c = 8 * j + cbase;
                float2 va = *(const float2*)(vA + c);
                float2 vb3 = *(const float2*)(vB + c);
                oacc[j][0] += pA[n] * va.x; oacc[j][1] += pA[n] * va.y;
                oacc[j][2] += pB[n] * vb3.x; oacc[j][3] += pB[n] * vb3.y;
            }
        }
        // ---- finalize + store split bf16 ----
        float i0 = 1.0f / l0, i1 = 1.0f / l1;
        size_t tok0 = (size_t)(b * SS + sA) * HH + h * 64;
        size_t tok1 = (size_t)(b * SS + sB) * HH + h * 64;
#pragma unroll
        for (int j = 0; j < 8; j++) {
            int c = 8 * j + cbase;
            uint32_t hi, lo;
            packsplit(oacc[j][0] * i0, oacc[j][1] * i0, hi, lo);
            *(uint32_t*)(ohi + tok0 + c) = hi;
            *(uint32_t*)(olo + tok0 + c) = lo;
            packsplit(oacc[j][2] * i1, oacc[j][3] * i1, hi, lo);
            *(uint32_t*)(ohi + tok1 + c) = hi;
            *(uint32_t*)(olo + tok1 + c) = lo;
        }
    }
}

// SiLU(gate)*up -> split bf16 pair
__global__ __launch_bounds__(256) void silu_split_kernel(
    const float* __restrict__ gu, __nv_bfloat16* __restrict__ hi,
    __nv_bfloat16* __restrict__ lo)
{
    int i = blockIdx.x * 256 + threadIdx.x;
    int row = i >> 13, col = i & 8191;
    float g = gu[(size_t)row * 16384 + col];
    float u = gu[(size_t)row * 16384 + 8192 + col];
    float a = g / (1.0f + expf(-g)) * u;
    __nv_bfloat16 hv, lv;
    split2(a, hv, lv);
    hi[i] = hv; lo[i] = lv;
}

// ================= launcher =================
extern "C" void kernel_launch(void* const* d_in, const int* in_sizes, int n_in,
                              void* d_out, int out_size)
{
    const float* input_emb     = (const float*)d_in[0];
    const float* hidden_states = (const float*)d_in[1];
    const float* cache_k       = (const float*)d_in[2];
    const float* cache_v       = (const float*)d_in[3];
    const int*   position_ids  = (const int*)d_in[5];
    const float* wq            = (const float*)d_in[6];
    const float* wk            = (const float*)d_in[7];
    const float* wv            = (const float*)d_in[8];
    const float* wo            = (const float*)d_in[9];
    const float* w_gate        = (const float*)d_in[10];
    const float* w_up          = (const float*)d_in[11];
    const float* w_down        = (const float*)d_in[12];
    const float* hidden_norm_w = (const float*)d_in[13];
    const float* input_ln_w    = (const float*)d_in[14];
    const float* post_ln_w     = (const float*)d_in[15];
    float* out = (float*)d_out;

    __nv_bfloat16 *xhi, *xlo, *wqkvh, *wqkvl, *woh, *wol, *wguh, *wgul, *wdnh, *wdnl;
    __nv_bfloat16 *ahi, *alo, *hnhi, *hnlo, *acth, *actl;
    __nv_bfloat16 *qhp, *qlp, *k0h, *k0l, *vthp, *vtlp;
    float *qkv, *q, *k, *v, *h2, *gu;
    cudaGetSymbolAddress((void**)&xhi, g_xhi);     cudaGetSymbolAddress((void**)&xlo, g_xlo);
    cudaGetSymbolAddress((void**)&wqkvh, g_wqkv_hi); cudaGetSymbolAddress((void**)&wqkvl, g_wqkv_lo);
    cudaGetSymbolAddress((void**)&woh, g_wo_hi);   cudaGetSymbolAddress((void**)&wol, g_wo_lo);
    cudaGetSymbolAddress((void**)&wguh, g_wgu_hi); cudaGetSymbolAddress((void**)&wgul, g_wgu_lo);
    cudaGetSymbolAddress((void**)&wdnh, g_wdn_hi); cudaGetSymbolAddress((void**)&wdnl, g_wdn_lo);
    cudaGetSymbolAddress((void**)&ahi, g_ahi);     cudaGetSymbolAddress((void**)&alo, g_alo);
    cudaGetSymbolAddress((void**)&hnhi, g_hnhi);   cudaGetSymbolAddress((void**)&hnlo, g_hnlo);
    cudaGetSymbolAddress((void**)&acth, g_acthi);  cudaGetSymbolAddress((void**)&actl, g_actlo);
    cudaGetSymbolAddress((void**)&qkv, g_qkv);
    cudaGetSymbolAddress((void**)&q, g_q);
    cudaGetSymbolAddress((void**)&k, g_k);
    cudaGetSymbolAddress((void**)&v, g_v);
    cudaGetSymbolAddress((void**)&h2, g_h2);
    cudaGetSymbolAddress((void**)&gu, g_gu);
    cudaGetSymbolAddress((void**)&qhp, g_qh);      cudaGetSymbolAddress((void**)&qlp, g_ql);
    cudaGetSymbolAddress((void**)&k0h, g_k0h);     cudaGetSymbolAddress((void**)&k0l, g_k0l);
    cudaGetSymbolAddress((void**)&vthp, g_vth);    cudaGetSymbolAddress((void**)&vtlp, g_vtl);

    cudaFuncSetAttribute(gemm_mma, cudaFuncAttributeMaxDynamicSharedMemorySize, GEMM_DSMEM);
    cudaFuncSetAttribute(attn_tc_kernel, cudaFuncAttributeMaxDynamicSharedMemorySize, ATTN2_DSMEM);

    // weight conversions
    convert_qkv_kernel<<<3072 * 4096 / 1024, 256>>>(wq, wk, wv, wqkvh, wqkvl);
    convert_split_kernel<<<2048 * 2048 / 1024, 256>>>(wo, woh, wol, 2048 * 2048);
    // attention operand prep: cache K[0] split + cache V[0] transpose-split
    convert_split_kernel<<<Bb * NHH * SS * DD / 1024, 256>>>(cache_k, k0h, k0l, Bb * NHH * SS * DD);
    transpose_v0_kernel<<<dim3(SS / 64, Bb * NHH), 256>>>(cache_v, vthp, vtlp);

    // 1. norms + concat (split bf16)
    rmsnorm_concat_kernel<<<TOK, 256>>>(input_emb, hidden_states, input_ln_w, hidden_norm_w, xhi, xlo);
    // 2. QKV GEMM (packed, N=3072)
    gemm_mma<<<dim3(3072 / 128, TOK / 128), 256, GEMM_DSMEM>>>(xhi, xlo, wqkvh, wqkvl, nullptr, qkv, 3072, 4096, 0);
    // 3. RoPE + reshape (+ q bf16 hi/lo)
    rope_kernel<<<TOK, 256>>>(qkv, position_ids, q, k, v, qhp, qlp);
    // 4. attention (tensor cores) -> split bf16
    attn_tc_kernel<<<dim3(SS / 64, NHH, Bb), 128, ATTN2_DSMEM>>>(
        qhp, qlp, k0h, k0l, vthp, vtlp, q, cache_k, cache_v, k, v, ahi, alo);
    // 5. out projection + residual
    gemm_mma<<<dim3(2048 / 128, TOK / 128), 256, GEMM_DSMEM>>>(ahi, alo, woh, wol, hidden_states, h2, 2048, 2048, 1);
    // 6. post-attn norm -> split bf16
    rmsnorm_split_kernel<<<TOK, 256>>>(h2, post_ln_w, hnhi, hnlo);
    // 7. gate|up weight converts + GEMM (packed, N=16384)
    convert_split_kernel<<<8192 * 2048 / 1024, 256>>>(w_gate, wguh, wgul, 8192 * 2048);
    convert_split_kernel<<<8192 * 2048 / 1024, 256>>>(w_up, wguh + 8192 * 2048, wgul + 8192 * 2048, 8192 * 2048);
    gemm_mma<<<dim3(16384 / 128, TOK / 128), 256, GEMM_DSMEM>>>(hnhi, hnlo, wguh, wgul, nullptr, gu, 16384, 2048, 0);
    // 8. SiLU * up -> split bf16
    silu_split_kernel<<<TOK * IIF / 256, 256>>>(gu, acth, actl);
    // 9. down projection + residual -> final output
    convert_split_kernel<<<2048 * 8192 / 1024, 256>>>(w_down, wdnh, wdnl, 2048 * 8192);
    gemm_mma<<<dim3(2048 / 128, TOK / 128), 256, GEMM_DSMEM>>>(acth, actl, wdnh, wdnl, h2, out, 2048, 8192, 1);

    (void)in_sizes; (void)n_in; (void)out_size;
}